// round 11
// baseline (speedup 1.0000x reference)
#include <cuda_runtime.h>
#include <cuda_fp16.h>

#define FM 0xffffffffu
#define SCALE_D 0.17677669529663688f  // 1/sqrt(32)

// ---- scratch (device globals; allocation is forbidden) ----
__device__ float  g_q0t[4*16384*256];
__device__ __half g_k0h[4*16384*256];
__device__ __half g_v0h[4*16384*256];
__device__ float  g_q1t[4*4096*256];
__device__ float  g_k1t[4*4096*256];
__device__ __half g_v1h[4*4096*256];
__device__ float  g_q2t[4*1024*256];
__device__ float  g_k2t[4*1024*256];
__device__ float  g_v2t[4*1024*256];
__device__ float  g_msg2[4*1024*8*32];
__device__ float  g_fin1[4*4096*8*32];
__device__ int    g_idx2[4*8*1024*16];
__device__ int    g_idx1[4*8*4096*8];

__device__ __forceinline__ unsigned ford(float f) {
    unsigned u = __float_as_uint(f);
    return (u & 0x80000000u) ? ~u : (u | 0x80000000u);
}
__device__ __forceinline__ unsigned long long ffma2(unsigned long long a,
                                                    unsigned long long b,
                                                    unsigned long long c) {
    unsigned long long d;
    asm("fma.rn.f32x2 %0, %1, %2, %3;" : "=l"(d) : "l"(a), "l"(b), "l"(c));
    return d;
}
__device__ __forceinline__ unsigned long long addf2(unsigned long long a,
                                                    unsigned long long b) {
    unsigned long long d;
    asm("add.rn.f32x2 %0, %1, %2;" : "=l"(d) : "l"(a), "l"(b));
    return d;
}
__device__ __forceinline__ float2 u2f2(unsigned long long a) {
    float2 r;
    asm("mov.b64 {%0, %1}, %2;" : "=f"(r.x), "=f"(r.y) : "l"(a));
    return r;
}
__device__ __forceinline__ unsigned long long f2u2(float x, float y) {
    unsigned long long r;
    asm("mov.b64 %0, {%1, %2};" : "=l"(r) : "f"(x), "f"(y));
    return r;
}
// convert uint4 (8 packed halves) -> two float4
__device__ __forceinline__ void h8_to_f8(uint4 r, float4* lo, float4* hi) {
    __half2 h0 = *(__half2*)&r.x, h1 = *(__half2*)&r.y;
    __half2 h2 = *(__half2*)&r.z, h3 = *(__half2*)&r.w;
    float2 f0 = __half22float2(h0), f1 = __half22float2(h1);
    float2 f2 = __half22float2(h2), f3 = __half22float2(h3);
    *lo = make_float4(f0.x, f0.y, f1.x, f1.y);
    *hi = make_float4(f2.x, f2.y, f3.x, f3.y);
}

// ---- transpose core (shared by standalone L2 kernel and fused kernel) ----
__device__ __forceinline__ void tr_core(char* smem_raw, const float* in,
                                        float* outf, __half* outh, int S,
                                        int b, int sblk, int cblk) {
    float (*sm)[132] = (float(*)[132])smem_raw;
    const int s0 = sblk * 128, c0 = cblk * 32;
    const int tid = threadIdx.x, tx = tid & 31, ty = tid >> 5;
    const float* ib = in + (size_t)b * 256 * S;
#pragma unroll
    for (int kk = 0; kk < 4; kk++) {
        int c = ty + 8 * kk;
        *(float4*)&sm[c][4 * tx] = *(const float4*)(ib + (size_t)(c0 + c) * S + s0 + 4 * tx);
    }
    __syncthreads();
    if (outh) {
        __half* ob = outh + (size_t)b * 256 * S;
#pragma unroll
        for (int m = 0; m < 4; m++) {
            int j = tid + 256 * m, sl = j >> 3, cf = j & 7;
            __half2 h0 = __floats2half2_rn(sm[4 * cf][sl], sm[4 * cf + 1][sl]);
            __half2 h1 = __floats2half2_rn(sm[4 * cf + 2][sl], sm[4 * cf + 3][sl]);
            uint2 st;
            st.x = *(unsigned*)&h0; st.y = *(unsigned*)&h1;
            *(uint2*)(ob + (size_t)(s0 + sl) * 256 + c0 + 4 * cf) = st;
        }
    } else {
        float* ob = outf + (size_t)b * 256 * S;
#pragma unroll
        for (int m = 0; m < 4; m++) {
            int j = tid + 256 * m, sl = j >> 3, cf = j & 7;
            float4 o = make_float4(sm[4 * cf][sl], sm[4 * cf + 1][sl],
                                   sm[4 * cf + 2][sl], sm[4 * cf + 3][sl]);
            *(float4*)(ob + (size_t)(s0 + sl) * 256 + c0 + 4 * cf) = o;
        }
    }
}

// ---- standalone L2 transpose (must precede coarse) ----
__global__ void __launch_bounds__(256) tr_l2(const float* __restrict__ q2,
                                             const float* __restrict__ k2,
                                             const float* __restrict__ v2) {
    __shared__ float sm[32][132];
    const int which = blockIdx.z >> 2, b = blockIdx.z & 3;
    const float* in = which == 0 ? q2 : which == 1 ? k2 : v2;
    float* outf = which == 0 ? g_q2t : which == 1 ? g_k2t : g_v2t;
    tr_core((char*)sm, in, outf, 0, 1024, b, blockIdx.x, blockIdx.y);
}

// ---- coarse device path: 2 q/warp, f32x2, 128-key tiles, cp.async --------
#define CP_STAGE(GBASE, SMEMT, TID)                                            \
    {                                                                          \
        _Pragma("unroll") for (int it_ = 0; it_ < 4; it_++) {                  \
            int i_ = (TID) + it_ * 256, key_ = i_ >> 3, f_ = i_ & 7;           \
            unsigned sa_ = (unsigned)__cvta_generic_to_shared(                 \
                (SMEMT) + (key_ * 36 + f_ * 4) * 4);                           \
            const float* g_ = (GBASE) + (size_t)key_ * 256 + f_ * 4;           \
            asm volatile("cp.async.cg.shared.global [%0], [%1], 16;\n" ::      \
                             "r"(sa_), "l"(g_));                               \
        }                                                                      \
        asm volatile("cp.async.commit_group;\n");                              \
    }

__device__ void coarse_path(char* smem_raw, int qtile, int head, int b) {
    float* As = (float*)smem_raw;  // [16][1024]
    const int tid = threadIdx.x, w = tid >> 5, lane = tid & 31;
    const int l0 = qtile * 16 + 2 * w;
    float* As0 = As + (2 * w) * 1024;
    float* As1 = As0 + 1024;
    char* tileA = smem_raw + 65536;
    char* tileB = tileA + 18432;

    const float* ktb = g_k2t + (size_t)b * 1024 * 256 + head * 32;
    const float* vtb = g_v2t + (size_t)b * 1024 * 256 + head * 32;

    // ---- pass 1: logits into As -----------------------------------------
    {
        unsigned long long q0[16], q1[16];
        const float* qp = g_q2t + ((size_t)(b * 1024 + l0)) * 256 + head * 32;
#pragma unroll
        for (int r = 0; r < 16; r++) {
            q0[r] = *(const unsigned long long*)(qp + 2 * r);
            q1[r] = *(const unsigned long long*)(qp + 256 + 2 * r);
        }
        CP_STAGE(ktb, tileA, tid);
#pragma unroll
        for (int t = 0; t < 8; t++) {
            char* cur = (t & 1) ? tileB : tileA;
            char* nxt = (t & 1) ? tileA : tileB;
            if (t < 7) {
                CP_STAGE(ktb + (size_t)(t + 1) * 128 * 256, nxt, tid);
                asm volatile("cp.async.wait_group 1;\n");
            } else {
                asm volatile("cp.async.wait_group 0;\n");
            }
            __syncthreads();
            const float (*ks)[36] = (const float(*)[36])cur;
#pragma unroll
            for (int j = 0; j < 4; j++) {
                int key = j * 32 + lane;
                const ulonglong2* kr = (const ulonglong2*)&ks[key][0];
                unsigned long long a0 = 0ull, a1 = 0ull;
#pragma unroll
                for (int r = 0; r < 8; r++) {
                    ulonglong2 kk = kr[r];
                    a0 = ffma2(q0[2 * r], kk.x, a0);
                    a0 = ffma2(q0[2 * r + 1], kk.y, a0);
                    a1 = ffma2(q1[2 * r], kk.x, a1);
                    a1 = ffma2(q1[2 * r + 1], kk.y, a1);
                }
                float2 f0 = u2f2(a0), f1 = u2f2(a1);
                As0[t * 128 + key] = f0.x + f0.y;
                As1[t * 128 + key] = f1.x + f1.y;
            }
            __syncthreads();
        }
    }

    // prefetch first V tile behind the topk/softmax phase
    CP_STAGE(vtb, tileA, tid);

    // ---- top-16 (raw logits; only the SET matters) + softmax -------------
    for (int qi = 0; qi < 2; qi++) {
        float* Aq = qi ? As1 : As0;
        float sc[32];
#pragma unroll
        for (int i = 0; i < 32; i++) sc[i] = Aq[i * 32 + lane];
        unsigned c1 = 0u, c2 = 0u; int i1 = 0, i2 = 0;
#pragma unroll
        for (int i = 0; i < 32; i++) {
            unsigned v = ford(sc[i]);
            if (v > c1) { c2 = c1; i2 = i1; c1 = v; i1 = i; }
            else if (v > c2) { c2 = v; i2 = i; }
        }
        int myidx = 0;
        for (int r = 0; r < 16; r++) {
            unsigned wm = __reduce_max_sync(FM, c1);
            unsigned ball = __ballot_sync(FM, c1 == wm);
            int src = __ffs(ball) - 1;
            int sli = __shfl_sync(FM, i1, src);
            if (lane == r) myidx = sli * 32 + src;
            if (lane == src) {
                if (c2 == 0u) {
                    unsigned a = 0u, bq = 0u; int ai = 0, bi = 0;
#pragma unroll
                    for (int i = 0; i < 32; i++) {
                        unsigned v = ford(sc[i]);
                        if (v < wm) {
                            if (v > a) { bq = a; bi = ai; a = v; ai = i; }
                            else if (v > bq) { bq = v; bi = i; }
                        }
                    }
                    c1 = a; i1 = ai; c2 = bq; i2 = bi;
                } else {
                    c1 = c2; i1 = i2; c2 = 0u;
                }
            }
        }
        if (lane < 16)
            g_idx2[((size_t)(b * 8 + head) * 1024 + l0 + qi) * 16 + lane] = myidx;
        float m = sc[0];
#pragma unroll
        for (int i = 1; i < 32; i++) m = fmaxf(m, sc[i]);
#pragma unroll
        for (int o = 16; o; o >>= 1) m = fmaxf(m, __shfl_xor_sync(FM, m, o));
        float sum = 0.f;
#pragma unroll
        for (int i = 0; i < 32; i++) { sc[i] = __expf((sc[i] - m) * SCALE_D); sum += sc[i]; }
#pragma unroll
        for (int o = 16; o; o >>= 1) sum += __shfl_xor_sync(FM, sum, o);
        float inv = 1.f / sum;
#pragma unroll
        for (int i = 0; i < 32; i++) Aq[i * 32 + lane] = sc[i] * inv;
    }

    // ---- pass 2: A @ V (packed, double buffered) -------------------------
    unsigned long long m0[16], m1[16];
#pragma unroll
    for (int r = 0; r < 16; r++) { m0[r] = 0ull; m1[r] = 0ull; }
#pragma unroll
    for (int t = 0; t < 8; t++) {
        char* cur = (t & 1) ? tileB : tileA;
        char* nxt = (t & 1) ? tileA : tileB;
        if (t < 7) {
            CP_STAGE(vtb + (size_t)(t + 1) * 128 * 256, nxt, tid);
            asm volatile("cp.async.wait_group 1;\n");
        } else {
            asm volatile("cp.async.wait_group 0;\n");
        }
        __syncthreads();
        const float (*ks)[36] = (const float(*)[36])cur;
#pragma unroll
        for (int j = 0; j < 4; j++) {
            int key = j * 32 + lane, gk = t * 128 + key;
            float a0s = As0[gk], a1s = As1[gk];
            unsigned long long a0 = f2u2(a0s, a0s), a1 = f2u2(a1s, a1s);
            const ulonglong2* vr = (const ulonglong2*)&ks[key][0];
#pragma unroll
            for (int r = 0; r < 8; r++) {
                ulonglong2 vv = vr[r];
                m0[2 * r]     = ffma2(a0, vv.x, m0[2 * r]);
                m0[2 * r + 1] = ffma2(a0, vv.y, m0[2 * r + 1]);
                m1[2 * r]     = ffma2(a1, vv.x, m1[2 * r]);
                m1[2 * r + 1] = ffma2(a1, vv.y, m1[2 * r + 1]);
            }
        }
        __syncthreads();
    }
#define RSU(M, OFF, HALF) { int bit = (lane & OFF) ? 1 : 0;                   \
    _Pragma("unroll") for (int r = 0; r < HALF; r++) {                        \
        unsigned long long lo = M[r], hi = M[HALF + r];                       \
        unsigned long long snd = bit ? lo : hi;                               \
        unsigned long long rcv = __shfl_xor_sync(FM, snd, OFF);               \
        M[r] = addf2(bit ? hi : lo, rcv); } }
#pragma unroll
    for (int qi = 0; qi < 2; qi++) {
        unsigned long long* M = qi ? m1 : m0;
        RSU(M, 16, 8) RSU(M, 8, 4) RSU(M, 4, 2) RSU(M, 2, 1)
        float2 f2 = u2f2(M[0]);
        float snd = (lane & 1) ? f2.x : f2.y;
        float rcv = __shfl_xor_sync(FM, snd, 1);
        float val = ((lane & 1) ? f2.y : f2.x) + rcv;
        g_msg2[((size_t)(b * 1024 + l0 + qi) * 8 + head) * 32 + lane] = val;
    }
#undef RSU
}

// ---- fused: [12288 trL0][3072 trL1][2048 coarse] -------------------------
__global__ void __launch_bounds__(256) fused_kernel(const float* __restrict__ q0,
                                                    const float* __restrict__ k0,
                                                    const float* __restrict__ v0,
                                                    const float* __restrict__ q1,
                                                    const float* __restrict__ k1,
                                                    const float* __restrict__ v1) {
    extern __shared__ __align__(16) char smem_raw[];
    int bx = blockIdx.x;
    if (bx < 12288) {  // L0 transpose
        int sblk = bx & 127, cblk = (bx >> 7) & 7, zz = bx >> 10;
        int which = zz >> 2, b = zz & 3;
        const float* in = which == 0 ? q0 : which == 1 ? k0 : v0;
        float* outf = which == 0 ? g_q0t : 0;
        __half* outh = which == 1 ? g_k0h : which == 2 ? g_v0h : 0;
        tr_core(smem_raw, in, outf, outh, 16384, b, sblk, cblk);
    } else if (bx < 15360) {  // L1 transpose
        int t = bx - 12288;
        int sblk = t & 31, cblk = (t >> 5) & 7, zz = t >> 8;
        int which = zz >> 2, b = zz & 3;
        const float* in = which == 0 ? q1 : which == 1 ? k1 : v1;
        float* outf = which == 0 ? g_q1t : which == 1 ? g_k1t : 0;
        __half* outh = which == 2 ? g_v1h : 0;
        tr_core(smem_raw, in, outf, outh, 4096, b, sblk, cblk);
    } else {  // coarse
        int cb = bx - 15360;
        coarse_path(smem_raw, cb & 63, (cb >> 6) & 7, cb >> 9);
    }
}

// ---- fine level 1 (64x64): 64 gathered keys, top-8, fused ws0/ws1 --------
__global__ void __launch_bounds__(128) fine1_kernel(const float* __restrict__ wt) {
    __shared__ __align__(16) float vs[4][64][36];
    __shared__ __align__(16) float aw[4][64][4];
    __shared__ __align__(16) float qw[4][4][32];
    const int tid = threadIdx.x, w = tid >> 5, lane = tid & 31;
    const int g = blockIdx.x*4 + w;
    const int b = g >> 13, r = g & 8191, h = r >> 10, l2 = r & 1023;
    const int r2 = l2 >> 5, c2 = l2 & 31;

    float w0 = wt[0], w1 = wt[1], w2 = wt[2];
    float wmx = fmaxf(w0, fmaxf(w1, w2));
    float e0 = __expf(w0-wmx), e1 = __expf(w1-wmx), e2 = __expf(w2-wmx);
    float ws0 = e0/(e0+e1+e2), ws1 = e1/(e0+e1+e2);

    int pid = g_idx2[((size_t)(b*8+h)*1024 + l2)*16 + (lane & 15)];
    int p0 = __shfl_sync(FM, pid, lane >> 2);
    int p1 = __shfl_sync(FM, pid, 8 + (lane >> 2));
    int cx = (lane >> 1) & 1, cy = lane & 1;
    int gid0 = (2*(p0>>5)+cx)*64 + 2*(p0&31)+cy;
    int gid1 = (2*(p1>>5)+cx)*64 + 2*(p1&31)+cy;

    const float*  kb  = g_k1t + (size_t)b*4096*256 + h*32;
    const __half* vbh = g_v1h + (size_t)b*4096*256 + h*32;
    float4 k0[8], k1[8];
#pragma unroll
    for (int f = 0; f < 8; f++) {
        k0[f] = *(const float4*)(kb + (size_t)gid0*256 + f*4);
        k1[f] = *(const float4*)(kb + (size_t)gid1*256 + f*4);
    }
    { int t = lane >> 3, f = (lane & 7)*4;
      int qpos = (2*r2 + (t>>1))*64 + 2*c2 + (t&1);
      *(float4*)&qw[w][t][f] = *(const float4*)(g_q1t + ((size_t)(b*4096+qpos))*256 + h*32 + f); }
    __syncwarp();

    float lg[2][4];
#pragma unroll
    for (int t = 0; t < 4; t++) {
        float a0 = 0.f, a1 = 0.f;
#pragma unroll
        for (int f = 0; f < 8; f++) {
            float4 qf = *(float4*)&qw[w][t][f*4];
            a0 += qf.x*k0[f].x + qf.y*k0[f].y + qf.z*k0[f].z + qf.w*k0[f].w;
            a1 += qf.x*k1[f].x + qf.y*k1[f].y + qf.z*k1[f].z + qf.w*k1[f].w;
        }
        lg[0][t] = a0*SCALE_D; lg[1][t] = a1*SCALE_D;
    }
    float av0[4], av1[4];
#pragma unroll
    for (int t = 0; t < 4; t++) {
        float m = fmaxf(lg[0][t], lg[1][t]);
#pragma unroll
        for (int o = 16; o; o >>= 1) m = fmaxf(m, __shfl_xor_sync(FM, m, o));
        float x0 = __expf(lg[0][t]-m), x1 = __expf(lg[1][t]-m);
        float s = x0 + x1;
#pragma unroll
        for (int o = 16; o; o >>= 1) s += __shfl_xor_sync(FM, s, o);
        av0[t] = x0/s; av1[t] = x1/s;
    }
    *(float4*)&aw[w][lane][0]    = make_float4(av0[0], av0[1], av0[2], av0[3]);
    *(float4*)&aw[w][lane+32][0] = make_float4(av1[0], av1[1], av1[2], av1[3]);

#pragma unroll
    for (int t = 0; t < 4; t++) {
        unsigned o0 = ford(lg[0][t]), o1 = ford(lg[1][t]);
        int keep = 0;
        for (int rr = 0; rr < 8; rr++) {
            unsigned lmx = max(o0, o1);
            unsigned wm = __reduce_max_sync(FM, lmx);
            unsigned ball = __ballot_sync(FM, lmx == wm);
            int src = __ffs(ball) - 1;
            int mysel = (o1 > o0) ? gid1 : gid0;
            int gsel = __shfl_sync(FM, mysel, src);
            if (lane == rr) keep = gsel;
            if (lane == src) { if (o1 > o0) o1 = 0u; else o0 = 0u; }
        }
        int qpos = (2*r2 + (t>>1))*64 + 2*c2 + (t&1);
        if (lane < 8) g_idx1[((size_t)(b*8+h)*4096 + qpos)*8 + lane] = keep;
    }
    {   // stage gathered V rows (fp16 -> fp32 smem)
        const uint4* s0 = (const uint4*)(vbh + (size_t)gid0*256);
        const uint4* s1 = (const uint4*)(vbh + (size_t)gid1*256);
#pragma unroll
        for (int f = 0; f < 4; f++) {
            float4 lo, hi;
            h8_to_f8(s0[f], &lo, &hi);
            *(float4*)&vs[w][lane][f*8]   = lo;
            *(float4*)&vs[w][lane][f*8+4] = hi;
            h8_to_f8(s1[f], &lo, &hi);
            *(float4*)&vs[w][lane+32][f*8]   = lo;
            *(float4*)&vs[w][lane+32][f*8+4] = hi;
        }
    }
    __syncwarp();
    float acc[4] = {0.f, 0.f, 0.f, 0.f};
#pragma unroll 8
    for (int k = 0; k < 64; k++) {
        float v = vs[w][k][lane];
        float4 a4 = *(float4*)&aw[w][k][0];
        acc[0] += a4.x*v; acc[1] += a4.y*v; acc[2] += a4.z*v; acc[3] += a4.w*v;
    }
    float m2 = g_msg2[((size_t)(b*1024+l2)*8 + h)*32 + lane] * ws0;
#pragma unroll
    for (int t = 0; t < 4; t++) {
        int qpos = (2*r2 + (t>>1))*64 + 2*c2 + (t&1);
        g_fin1[((size_t)(b*4096+qpos)*8 + h)*32 + lane] = m2 + acc[t]*ws1;
    }
}

// ---- fine level 0 (128x128): 32 gathered fp16 keys, fused final combine --
__global__ void __launch_bounds__(256) fine0_kernel(const float* __restrict__ wt,
                                                    float* __restrict__ out) {
    __shared__ __align__(16) float vs[8][32][36];
    __shared__ __align__(16) float aw[8][32][4];
    __shared__ __align__(16) float qw[8][4][32];
    const int tid = threadIdx.x, w = tid >> 5, lane = tid & 31;
    const int g = blockIdx.x*8 + w;
    const int b = g >> 15, r = g & 32767, h = r >> 12, l1 = r & 4095;
    const int R = l1 >> 6, C = l1 & 63;

    float w0 = wt[0], w1 = wt[1], w2 = wt[2];
    float wmx = fmaxf(w0, fmaxf(w1, w2));
    float e0 = __expf(w0-wmx), e1 = __expf(w1-wmx), e2 = __expf(w2-wmx);
    float ws2 = e2/(e0+e1+e2);

    int p = g_idx1[((size_t)(b*8+h)*4096 + l1)*8 + (lane >> 2)];
    int cx = (lane >> 1) & 1, cy = lane & 1;
    int gid = (2*(p>>6)+cx)*128 + 2*(p&63)+cy;

    const __half* kbh = g_k0h + (size_t)b*16384*256 + h*32;
    const __half* vbh = g_v0h + (size_t)b*16384*256 + h*32;
    float4 kr[8];
    {
        const uint4* ks = (const uint4*)(kbh + (size_t)gid*256);
#pragma unroll
        for (int f = 0; f < 4; f++) h8_to_f8(ks[f], &kr[2*f], &kr[2*f+1]);
    }
    { int t = lane >> 3, f = (lane & 7)*4;
      int qpos = (2*R + (t>>1))*128 + 2*C + (t&1);
      *(float4*)&qw[w][t][f] = *(const float4*)(g_q0t + ((size_t)(b*16384+qpos))*256 + h*32 + f); }
    __syncwarp();

    float lg[4];
#pragma unroll
    for (int t = 0; t < 4; t++) {
        float a = 0.f;
#pragma unroll
        for (int f = 0; f < 8; f++) {
            float4 qf = *(float4*)&qw[w][t][f*4];
            a += qf.x*kr[f].x + qf.y*kr[f].y + qf.z*kr[f].z + qf.w*kr[f].w;
        }
        lg[t] = a*SCALE_D;
    }
    float av[4];
#pragma unroll
    for (int t = 0; t < 4; t++) {
        float m = lg[t];
#pragma unroll
        for (int o = 16; o; o >>= 1) m = fmaxf(m, __shfl_xor_sync(FM, m, o));
        float x = __expf(lg[t]-m);
        float s = x;
#pragma unroll
        for (int o = 16; o; o >>= 1) s += __shfl_xor_sync(FM, s, o);
        av[t] = x/s;
    }
    *(float4*)&aw[w][lane][0] = make_float4(av[0], av[1], av[2], av[3]);
    {
        const uint4* s0 = (const uint4*)(vbh + (size_t)gid*256);
#pragma unroll
        for (int f = 0; f < 4; f++) {
            float4 lo, hi;
            h8_to_f8(s0[f], &lo, &hi);
            *(float4*)&vs[w][lane][f*8]   = lo;
            *(float4*)&vs[w][lane][f*8+4] = hi;
        }
    }
    __syncwarp();
    float acc[4] = {0.f, 0.f, 0.f, 0.f};
#pragma unroll 8
    for (int k = 0; k < 32; k++) {
        float v = vs[w][k][lane];
        float4 a4 = *(float4*)&aw[w][k][0];
        acc[0] += a4.x*v; acc[1] += a4.y*v; acc[2] += a4.z*v; acc[3] += a4.w*v;
    }
    float base = g_fin1[((size_t)(b*4096+l1)*8 + h)*32 + lane];
#pragma unroll
    for (int t = 0; t < 4; t++) {
        int qpos = (2*R + (t>>1))*128 + 2*C + (t&1);
        out[((size_t)(b*16384+qpos)*8 + h)*32 + lane] = base + acc[t]*ws2;
    }
}

extern "C" void kernel_launch(void* const* d_in, const int* in_sizes, int n_in,
                              void* d_out, int out_size) {
    const float* q0 = (const float*)d_in[0];
    const float* q1 = (const float*)d_in[1];
    const float* q2 = (const float*)d_in[2];
    const float* k0 = (const float*)d_in[3];
    const float* k1 = (const float*)d_in[4];
    const float* k2 = (const float*)d_in[5];
    const float* v0 = (const float*)d_in[6];
    const float* v1 = (const float*)d_in[7];
    const float* v2 = (const float*)d_in[8];
    const float* wt = (const float*)d_in[9];
    static int smem_set = 0;
    if (!smem_set) {
        cudaFuncSetAttribute(fused_kernel,
                             cudaFuncAttributeMaxDynamicSharedMemorySize, 102400);
        smem_set = 1;
    }
    tr_l2<<<dim3(8, 8, 12), 256>>>(q2, k2, v2);
    fused_kernel<<<17408, 256, 102400>>>(q0, k0, v0, q1, k1, v1);
    fine1_kernel<<<8192, 128>>>(wt);
    fine0_kernel<<<16384, 256>>>(wt, (float*)d_out);
}

// round 12
// speedup vs baseline: 1.7097x; 1.7097x over previous
#include <cuda_runtime.h>
#include <cuda_fp16.h>

#define FM 0xffffffffu
#define SCALE_D 0.17677669529663688f  // 1/sqrt(32)

// ---- scratch (device globals; allocation is forbidden) ----
__device__ float  g_q0t[4*16384*256];
__device__ __half g_k0h[4*16384*256];
__device__ __half g_v0h[4*16384*256];
__device__ float  g_q1t[4*4096*256];
__device__ float  g_k1t[4*4096*256];
__device__ __half g_v1h[4*4096*256];
__device__ float  g_q2t[4*1024*256];
__device__ float  g_k2t[4*1024*256];
__device__ float  g_v2t[4*1024*256];
__device__ float  g_msg2[4*1024*8*32];
__device__ float  g_fin1[4*4096*8*32];
__device__ int    g_idx2[4*8*1024*16];
__device__ int    g_idx1[4*8*4096*8];

__device__ __forceinline__ unsigned ford(float f) {
    unsigned u = __float_as_uint(f);
    return (u & 0x80000000u) ? ~u : (u | 0x80000000u);
}
__device__ __forceinline__ unsigned long long ffma2(unsigned long long a,
                                                    unsigned long long b,
                                                    unsigned long long c) {
    unsigned long long d;
    asm("fma.rn.f32x2 %0, %1, %2, %3;" : "=l"(d) : "l"(a), "l"(b), "l"(c));
    return d;
}
__device__ __forceinline__ unsigned long long addf2(unsigned long long a,
                                                    unsigned long long b) {
    unsigned long long d;
    asm("add.rn.f32x2 %0, %1, %2;" : "=l"(d) : "l"(a), "l"(b));
    return d;
}
__device__ __forceinline__ float2 u2f2(unsigned long long a) {
    float2 r;
    asm("mov.b64 {%0, %1}, %2;" : "=f"(r.x), "=f"(r.y) : "l"(a));
    return r;
}
__device__ __forceinline__ unsigned long long f2u2(float x, float y) {
    unsigned long long r;
    asm("mov.b64 %0, {%1, %2};" : "=l"(r) : "f"(x), "f"(y));
    return r;
}
// convert uint4 (8 packed halves) -> two float4
__device__ __forceinline__ void h8_to_f8(uint4 r, float4* lo, float4* hi) {
    __half2 h0 = *(__half2*)&r.x, h1 = *(__half2*)&r.y;
    __half2 h2 = *(__half2*)&r.z, h3 = *(__half2*)&r.w;
    float2 f0 = __half22float2(h0), f1 = __half22float2(h1);
    float2 f2 = __half22float2(h2), f3 = __half22float2(h3);
    *lo = make_float4(f0.x, f0.y, f1.x, f1.y);
    *hi = make_float4(f2.x, f2.y, f3.x, f3.y);
}

// ---- float4 transpose (b,256,S) -> (b,S,256); fp16 out for k0,v0,v1 ------
__global__ void __launch_bounds__(256) tr_fast(const float* __restrict__ q,
                                               const float* __restrict__ k,
                                               const float* __restrict__ v, int S) {
    __shared__ float sm[32][132];
    const int which = blockIdx.z >> 2, b = blockIdx.z & 3;
    const float* in = which == 0 ? q : which == 1 ? k : v;
    float* outf = 0; __half* outh = 0;
    if (S == 16384) {
        if (which == 0) outf = g_q0t;
        else if (which == 1) outh = g_k0h;
        else outh = g_v0h;
    } else if (S == 4096) {
        if (which == 0) outf = g_q1t;
        else if (which == 1) outf = g_k1t;
        else outh = g_v1h;
    } else {
        outf = which == 0 ? g_q2t : which == 1 ? g_k2t : g_v2t;
    }
    const int s0 = blockIdx.x * 128, c0 = blockIdx.y * 32;
    const int tid = threadIdx.x, tx = tid & 31, ty = tid >> 5;
    const float* ib = in + (size_t)b * 256 * S;
#pragma unroll
    for (int kk = 0; kk < 4; kk++) {
        int c = ty + 8 * kk;
        *(float4*)&sm[c][4 * tx] = *(const float4*)(ib + (size_t)(c0 + c) * S + s0 + 4 * tx);
    }
    __syncthreads();
    if (outh) {
        __half* ob = outh + (size_t)b * 256 * S;
#pragma unroll
        for (int m = 0; m < 4; m++) {
            int j = tid + 256 * m, sl = j >> 3, cf = j & 7;
            __half2 h0 = __floats2half2_rn(sm[4 * cf][sl], sm[4 * cf + 1][sl]);
            __half2 h1 = __floats2half2_rn(sm[4 * cf + 2][sl], sm[4 * cf + 3][sl]);
            uint2 st;
            st.x = *(unsigned*)&h0; st.y = *(unsigned*)&h1;
            *(uint2*)(ob + (size_t)(s0 + sl) * 256 + c0 + 4 * cf) = st;
        }
    } else {
        float* ob = outf + (size_t)b * 256 * S;
#pragma unroll
        for (int m = 0; m < 4; m++) {
            int j = tid + 256 * m, sl = j >> 3, cf = j & 7;
            float4 o = make_float4(sm[4 * cf][sl], sm[4 * cf + 1][sl],
                                   sm[4 * cf + 2][sl], sm[4 * cf + 3][sl]);
            *(float4*)(ob + (size_t)(s0 + sl) * 256 + c0 + 4 * cf) = o;
        }
    }
}

// ---- coarse: 2 q/warp, f32x2, 128-key tiles, cp.async double buffer ------
#define CP_STAGE(GBASE, SMEMT, TID)                                            \
    {                                                                          \
        _Pragma("unroll") for (int it_ = 0; it_ < 4; it_++) {                  \
            int i_ = (TID) + it_ * 256, key_ = i_ >> 3, f_ = i_ & 7;           \
            unsigned sa_ = (unsigned)__cvta_generic_to_shared(                 \
                (SMEMT) + (key_ * 36 + f_ * 4) * 4);                           \
            const float* g_ = (GBASE) + (size_t)key_ * 256 + f_ * 4;           \
            asm volatile("cp.async.cg.shared.global [%0], [%1], 16;\n" ::      \
                             "r"(sa_), "l"(g_));                               \
        }                                                                      \
        asm volatile("cp.async.commit_group;\n");                              \
    }

__global__ void __launch_bounds__(256) coarse_kernel() {
    extern __shared__ __align__(16) char smem_raw[];
    float* As = (float*)smem_raw;  // [16][1024]
    const int head = blockIdx.y, b = blockIdx.z;
    const int tid = threadIdx.x, w = tid >> 5, lane = tid & 31;
    const int l0 = blockIdx.x * 16 + 2 * w;
    float* As0 = As + (2 * w) * 1024;
    float* As1 = As0 + 1024;
    char* tileA = smem_raw + 65536;
    char* tileB = tileA + 18432;

    const float* ktb = g_k2t + (size_t)b * 1024 * 256 + head * 32;
    const float* vtb = g_v2t + (size_t)b * 1024 * 256 + head * 32;

    // ---- pass 1: logits into As -----------------------------------------
    {
        unsigned long long q0[16], q1[16];
        const float* qp = g_q2t + ((size_t)(b * 1024 + l0)) * 256 + head * 32;
#pragma unroll
        for (int r = 0; r < 16; r++) {
            q0[r] = *(const unsigned long long*)(qp + 2 * r);
            q1[r] = *(const unsigned long long*)(qp + 256 + 2 * r);
        }
        CP_STAGE(ktb, tileA, tid);
#pragma unroll
        for (int t = 0; t < 8; t++) {
            char* cur = (t & 1) ? tileB : tileA;
            char* nxt = (t & 1) ? tileA : tileB;
            if (t < 7) {
                CP_STAGE(ktb + (size_t)(t + 1) * 128 * 256, nxt, tid);
                asm volatile("cp.async.wait_group 1;\n");
            } else {
                asm volatile("cp.async.wait_group 0;\n");
            }
            __syncthreads();
            const float (*ks)[36] = (const float(*)[36])cur;
#pragma unroll
            for (int j = 0; j < 4; j++) {
                int key = j * 32 + lane;
                const ulonglong2* kr = (const ulonglong2*)&ks[key][0];
                unsigned long long a0 = 0ull, a1 = 0ull;
#pragma unroll
                for (int r = 0; r < 8; r++) {
                    ulonglong2 kk = kr[r];
                    a0 = ffma2(q0[2 * r], kk.x, a0);
                    a0 = ffma2(q0[2 * r + 1], kk.y, a0);
                    a1 = ffma2(q1[2 * r], kk.x, a1);
                    a1 = ffma2(q1[2 * r + 1], kk.y, a1);
                }
                float2 f0 = u2f2(a0), f1 = u2f2(a1);
                As0[t * 128 + key] = f0.x + f0.y;
                As1[t * 128 + key] = f1.x + f1.y;
            }
            __syncthreads();
        }
    }

    // prefetch first V tile behind the topk/softmax phase
    CP_STAGE(vtb, tileA, tid);

    // ---- top-16 (raw logits; only the SET matters) + softmax -------------
    for (int qi = 0; qi < 2; qi++) {
        float* Aq = qi ? As1 : As0;
        float sc[32];
#pragma unroll
        for (int i = 0; i < 32; i++) sc[i] = Aq[i * 32 + lane];
        unsigned c1 = 0u, c2 = 0u; int i1 = 0, i2 = 0;
#pragma unroll
        for (int i = 0; i < 32; i++) {
            unsigned v = ford(sc[i]);
            if (v > c1) { c2 = c1; i2 = i1; c1 = v; i1 = i; }
            else if (v > c2) { c2 = v; i2 = i; }
        }
        int myidx = 0;
        for (int r = 0; r < 16; r++) {
            unsigned wm = __reduce_max_sync(FM, c1);
            unsigned ball = __ballot_sync(FM, c1 == wm);
            int src = __ffs(ball) - 1;
            int sli = __shfl_sync(FM, i1, src);
            if (lane == r) myidx = sli * 32 + src;
            if (lane == src) {
                if (c2 == 0u) {
                    unsigned a = 0u, bq = 0u; int ai = 0, bi = 0;
#pragma unroll
                    for (int i = 0; i < 32; i++) {
                        unsigned v = ford(sc[i]);
                        if (v < wm) {
                            if (v > a) { bq = a; bi = ai; a = v; ai = i; }
                            else if (v > bq) { bq = v; bi = i; }
                        }
                    }
                    c1 = a; i1 = ai; c2 = bq; i2 = bi;
                } else {
                    c1 = c2; i1 = i2; c2 = 0u;
                }
            }
        }
        if (lane < 16)
            g_idx2[((size_t)(b * 8 + head) * 1024 + l0 + qi) * 16 + lane] = myidx;
        float m = sc[0];
#pragma unroll
        for (int i = 1; i < 32; i++) m = fmaxf(m, sc[i]);
#pragma unroll
        for (int o = 16; o; o >>= 1) m = fmaxf(m, __shfl_xor_sync(FM, m, o));
        float sum = 0.f;
#pragma unroll
        for (int i = 0; i < 32; i++) { sc[i] = __expf((sc[i] - m) * SCALE_D); sum += sc[i]; }
#pragma unroll
        for (int o = 16; o; o >>= 1) sum += __shfl_xor_sync(FM, sum, o);
        float inv = 1.f / sum;
#pragma unroll
        for (int i = 0; i < 32; i++) Aq[i * 32 + lane] = sc[i] * inv;
    }

    // ---- pass 2: A @ V (packed, double buffered) -------------------------
    unsigned long long m0[16], m1[16];
#pragma unroll
    for (int r = 0; r < 16; r++) { m0[r] = 0ull; m1[r] = 0ull; }
#pragma unroll
    for (int t = 0; t < 8; t++) {
        char* cur = (t & 1) ? tileB : tileA;
        char* nxt = (t & 1) ? tileA : tileB;
        if (t < 7) {
            CP_STAGE(vtb + (size_t)(t + 1) * 128 * 256, nxt, tid);
            asm volatile("cp.async.wait_group 1;\n");
        } else {
            asm volatile("cp.async.wait_group 0;\n");
        }
        __syncthreads();
        const float (*ks)[36] = (const float(*)[36])cur;
#pragma unroll
        for (int j = 0; j < 4; j++) {
            int key = j * 32 + lane, gk = t * 128 + key;
            float a0s = As0[gk], a1s = As1[gk];
            unsigned long long a0 = f2u2(a0s, a0s), a1 = f2u2(a1s, a1s);
            const ulonglong2* vr = (const ulonglong2*)&ks[key][0];
#pragma unroll
            for (int r = 0; r < 8; r++) {
                ulonglong2 vv = vr[r];
                m0[2 * r]     = ffma2(a0, vv.x, m0[2 * r]);
                m0[2 * r + 1] = ffma2(a0, vv.y, m0[2 * r + 1]);
                m1[2 * r]     = ffma2(a1, vv.x, m1[2 * r]);
                m1[2 * r + 1] = ffma2(a1, vv.y, m1[2 * r + 1]);
            }
        }
        __syncthreads();
    }
#define RSU(M, OFF, HALF) { int bit = (lane & OFF) ? 1 : 0;                   \
    _Pragma("unroll") for (int r = 0; r < HALF; r++) {                        \
        unsigned long long lo = M[r], hi = M[HALF + r];                       \
        unsigned long long snd = bit ? lo : hi;                               \
        unsigned long long rcv = __shfl_xor_sync(FM, snd, OFF);               \
        M[r] = addf2(bit ? hi : lo, rcv); } }
#pragma unroll
    for (int qi = 0; qi < 2; qi++) {
        unsigned long long* M = qi ? m1 : m0;
        RSU(M, 16, 8) RSU(M, 8, 4) RSU(M, 4, 2) RSU(M, 2, 1)
        float2 f2 = u2f2(M[0]);
        float snd = (lane & 1) ? f2.x : f2.y;
        float rcv = __shfl_xor_sync(FM, snd, 1);
        float val = ((lane & 1) ? f2.y : f2.x) + rcv;
        g_msg2[((size_t)(b * 1024 + l0 + qi) * 8 + head) * 32 + lane] = val;
    }
#undef RSU
}

// ---- fine level 1 (64x64): 64 gathered keys, top-8, fused ws0/ws1 --------
// V staged in smem as fp16, rows padded to 34 halves (conflict-free).
__global__ void __launch_bounds__(128) fine1_kernel(const float* __restrict__ wt) {
    __shared__ __align__(16) __half vsh[4][64][34];
    __shared__ __align__(16) float aw[4][64][4];
    __shared__ __align__(16) float qw[4][4][32];
    const int tid = threadIdx.x, w = tid >> 5, lane = tid & 31;
    const int g = blockIdx.x*4 + w;
    const int b = g >> 13, r = g & 8191, h = r >> 10, l2 = r & 1023;
    const int r2 = l2 >> 5, c2 = l2 & 31;

    float w0 = wt[0], w1 = wt[1], w2 = wt[2];
    float wmx = fmaxf(w0, fmaxf(w1, w2));
    float e0 = __expf(w0-wmx), e1 = __expf(w1-wmx), e2 = __expf(w2-wmx);
    float ws0 = e0/(e0+e1+e2), ws1 = e1/(e0+e1+e2);

    int pid = g_idx2[((size_t)(b*8+h)*1024 + l2)*16 + (lane & 15)];
    int p0 = __shfl_sync(FM, pid, lane >> 2);
    int p1 = __shfl_sync(FM, pid, 8 + (lane >> 2));
    int cx = (lane >> 1) & 1, cy = lane & 1;
    int gid0 = (2*(p0>>5)+cx)*64 + 2*(p0&31)+cy;
    int gid1 = (2*(p1>>5)+cx)*64 + 2*(p1&31)+cy;

    const float*  kb  = g_k1t + (size_t)b*4096*256 + h*32;
    const __half* vbh = g_v1h + (size_t)b*4096*256 + h*32;
    float4 k0[8], k1[8];
#pragma unroll
    for (int f = 0; f < 8; f++) {
        k0[f] = *(const float4*)(kb + (size_t)gid0*256 + f*4);
        k1[f] = *(const float4*)(kb + (size_t)gid1*256 + f*4);
    }
    { int t = lane >> 3, f = (lane & 7)*4;
      int qpos = (2*r2 + (t>>1))*64 + 2*c2 + (t&1);
      *(float4*)&qw[w][t][f] = *(const float4*)(g_q1t + ((size_t)(b*4096+qpos))*256 + h*32 + f); }
    __syncwarp();

    float lg[2][4];
#pragma unroll
    for (int t = 0; t < 4; t++) {
        float a0 = 0.f, a1 = 0.f;
#pragma unroll
        for (int f = 0; f < 8; f++) {
            float4 qf = *(float4*)&qw[w][t][f*4];
            a0 += qf.x*k0[f].x + qf.y*k0[f].y + qf.z*k0[f].z + qf.w*k0[f].w;
            a1 += qf.x*k1[f].x + qf.y*k1[f].y + qf.z*k1[f].z + qf.w*k1[f].w;
        }
        lg[0][t] = a0*SCALE_D; lg[1][t] = a1*SCALE_D;
    }
    float av0[4], av1[4];
#pragma unroll
    for (int t = 0; t < 4; t++) {
        float m = fmaxf(lg[0][t], lg[1][t]);
#pragma unroll
        for (int o = 16; o; o >>= 1) m = fmaxf(m, __shfl_xor_sync(FM, m, o));
        float x0 = __expf(lg[0][t]-m), x1 = __expf(lg[1][t]-m);
        float s = x0 + x1;
#pragma unroll
        for (int o = 16; o; o >>= 1) s += __shfl_xor_sync(FM, s, o);
        av0[t] = x0/s; av1[t] = x1/s;
    }
    *(float4*)&aw[w][lane][0]    = make_float4(av0[0], av0[1], av0[2], av0[3]);
    *(float4*)&aw[w][lane+32][0] = make_float4(av1[0], av1[1], av1[2], av1[3]);

#pragma unroll
    for (int t = 0; t < 4; t++) {
        unsigned o0 = ford(lg[0][t]), o1 = ford(lg[1][t]);
        int keep = 0;
        for (int rr = 0; rr < 8; rr++) {
            unsigned lmx = max(o0, o1);
            unsigned wm = __reduce_max_sync(FM, lmx);
            unsigned ball = __ballot_sync(FM, lmx == wm);
            int src = __ffs(ball) - 1;
            int mysel = (o1 > o0) ? gid1 : gid0;
            int gsel = __shfl_sync(FM, mysel, src);
            if (lane == rr) keep = gsel;
            if (lane == src) { if (o1 > o0) o1 = 0u; else o0 = 0u; }
        }
        int qpos = (2*r2 + (t>>1))*64 + 2*c2 + (t&1);
        if (lane < 8) g_idx1[((size_t)(b*8+h)*4096 + qpos)*8 + lane] = keep;
    }
    {   // stage gathered V rows as fp16 (half2 stores, conflict-free)
        const uint4* s0 = (const uint4*)(vbh + (size_t)gid0*256);
        const uint4* s1 = (const uint4*)(vbh + (size_t)gid1*256);
        unsigned* r0 = (unsigned*)&vsh[w][lane][0];
        unsigned* r1 = (unsigned*)&vsh[w][lane + 32][0];
#pragma unroll
        for (int f = 0; f < 4; f++) {
            uint4 a = s0[f];
            r0[f*4+0] = a.x; r0[f*4+1] = a.y; r0[f*4+2] = a.z; r0[f*4+3] = a.w;
            uint4 c = s1[f];
            r1[f*4+0] = c.x; r1[f*4+1] = c.y; r1[f*4+2] = c.z; r1[f*4+3] = c.w;
        }
    }
    __syncwarp();
    float acc[4] = {0.f, 0.f, 0.f, 0.f};
    const __half* vflat = &vsh[w][0][0];
#pragma unroll 8
    for (int k = 0; k < 64; k++) {
        float v = __half2float(vflat[k * 34 + lane]);
        float4 a4 = *(float4*)&aw[w][k][0];
        acc[0] += a4.x*v; acc[1] += a4.y*v; acc[2] += a4.z*v; acc[3] += a4.w*v;
    }
    float m2 = g_msg2[((size_t)(b*1024+l2)*8 + h)*32 + lane] * ws0;
#pragma unroll
    for (int t = 0; t < 4; t++) {
        int qpos = (2*r2 + (t>>1))*64 + 2*c2 + (t&1);
        g_fin1[((size_t)(b*4096+qpos)*8 + h)*32 + lane] = m2 + acc[t]*ws1;
    }
}

// ---- fine level 0 (128x128): 32 gathered fp16 keys, fused final combine --
__global__ void __launch_bounds__(256) fine0_kernel(const float* __restrict__ wt,
                                                    float* __restrict__ out) {
    __shared__ __align__(16) __half vsh[8][32][34];
    __shared__ __align__(16) float aw[8][32][4];
    __shared__ __align__(16) float qw[8][4][32];
    const int tid = threadIdx.x, w = tid >> 5, lane = tid & 31;
    const int g = blockIdx.x*8 + w;
    const int b = g >> 15, r = g & 32767, h = r >> 12, l1 = r & 4095;
    const int R = l1 >> 6, C = l1 & 63;

    float w0 = wt[0], w1 = wt[1], w2 = wt[2];
    float wmx = fmaxf(w0, fmaxf(w1, w2));
    float e0 = __expf(w0-wmx), e1 = __expf(w1-wmx), e2 = __expf(w2-wmx);
    float ws2 = e2/(e0+e1+e2);

    int p = g_idx1[((size_t)(b*8+h)*4096 + l1)*8 + (lane >> 2)];
    int cx = (lane >> 1) & 1, cy = lane & 1;
    int gid = (2*(p>>6)+cx)*128 + 2*(p&63)+cy;

    const __half* kbh = g_k0h + (size_t)b*16384*256 + h*32;
    const __half* vbh = g_v0h + (size_t)b*16384*256 + h*32;
    float4 kr[8];
    {
        const uint4* ks = (const uint4*)(kbh + (size_t)gid*256);
#pragma unroll
        for (int f = 0; f < 4; f++) h8_to_f8(ks[f], &kr[2*f], &kr[2*f+1]);
    }
    { int t = lane >> 3, f = (lane & 7)*4;
      int qpos = (2*R + (t>>1))*128 + 2*C + (t&1);
      *(float4*)&qw[w][t][f] = *(const float4*)(g_q0t + ((size_t)(b*16384+qpos))*256 + h*32 + f); }
    __syncwarp();

    float lg[4];
#pragma unroll
    for (int t = 0; t < 4; t++) {
        float a = 0.f;
#pragma unroll
        for (int f = 0; f < 8; f++) {
            float4 qf = *(float4*)&qw[w][t][f*4];
            a += qf.x*kr[f].x + qf.y*kr[f].y + qf.z*kr[f].z + qf.w*kr[f].w;
        }
        lg[t] = a*SCALE_D;
    }
    float av[4];
#pragma unroll
    for (int t = 0; t < 4; t++) {
        float m = lg[t];
#pragma unroll
        for (int o = 16; o; o >>= 1) m = fmaxf(m, __shfl_xor_sync(FM, m, o));
        float x = __expf(lg[t]-m);
        float s = x;
#pragma unroll
        for (int o = 16; o; o >>= 1) s += __shfl_xor_sync(FM, s, o);
        av[t] = x/s;
    }
    *(float4*)&aw[w][lane][0] = make_float4(av[0], av[1], av[2], av[3]);
    {   // stage gathered V row as fp16 (half2 stores, conflict-free)
        const uint4* s0 = (const uint4*)(vbh + (size_t)gid*256);
        unsigned* r0 = (unsigned*)&vsh[w][lane][0];
#pragma unroll
        for (int f = 0; f < 4; f++) {
            uint4 a = s0[f];
            r0[f*4+0] = a.x; r0[f*4+1] = a.y; r0[f*4+2] = a.z; r0[f*4+3] = a.w;
        }
    }
    __syncwarp();
    float acc[4] = {0.f, 0.f, 0.f, 0.f};
    const __half* vflat = &vsh[w][0][0];
#pragma unroll 8
    for (int k = 0; k < 32; k++) {
        float v = __half2float(vflat[k * 34 + lane]);
        float4 a4 = *(float4*)&aw[w][k][0];
        acc[0] += a4.x*v; acc[1] += a4.y*v; acc[2] += a4.z*v; acc[3] += a4.w*v;
    }
    float base = g_fin1[((size_t)(b*4096+l1)*8 + h)*32 + lane];
#pragma unroll
    for (int t = 0; t < 4; t++) {
        int qpos = (2*R + (t>>1))*128 + 2*C + (t&1);
        out[((size_t)(b*16384+qpos)*8 + h)*32 + lane] = base + acc[t]*ws2;
    }
}

extern "C" void kernel_launch(void* const* d_in, const int* in_sizes, int n_in,
                              void* d_out, int out_size) {
    const float* q0 = (const float*)d_in[0];
    const float* q1 = (const float*)d_in[1];
    const float* q2 = (const float*)d_in[2];
    const float* k0 = (const float*)d_in[3];
    const float* k1 = (const float*)d_in[4];
    const float* k2 = (const float*)d_in[5];
    const float* v0 = (const float*)d_in[6];
    const float* v1 = (const float*)d_in[7];
    const float* v2 = (const float*)d_in[8];
    const float* wt = (const float*)d_in[9];
    static int smem_set = 0;
    if (!smem_set) {
        cudaFuncSetAttribute(coarse_kernel,
                             cudaFuncAttributeMaxDynamicSharedMemorySize, 102400);
        smem_set = 1;
    }
    tr_fast<<<dim3(128, 8, 12), 256>>>(q0, k0, v0, 16384);
    tr_fast<<<dim3(32, 8, 12), 256>>>(q1, k1, v1, 4096);
    tr_fast<<<dim3(8, 8, 12), 256>>>(q2, k2, v2, 1024);
    coarse_kernel<<<dim3(64, 8, 4), 256, 102400>>>();
    fine1_kernel<<<8192, 128>>>(wt);
    fine0_kernel<<<16384, 256>>>(wt, (float*)d_out);
}

// round 14
// speedup vs baseline: 2.1019x; 1.2294x over previous
#include <cuda_runtime.h>
#include <cuda_fp16.h>

#define FM 0xffffffffu
#define SCALE_D 0.17677669529663688f  // 1/sqrt(32)

// ---- scratch (device globals; allocation is forbidden) ----
__device__ float  g_q0t[4*16384*256];
__device__ __half g_k0h[4*16384*256];
__device__ __half g_v0h[4*16384*256];
__device__ float  g_q1t[4*4096*256];
__device__ float  g_k1t[4*4096*256];
__device__ __half g_v1h[4*4096*256];
__device__ float  g_q2t[4*1024*256];
__device__ float  g_k2t[4*1024*256];
__device__ float  g_v2t[4*1024*256];
__device__ float  g_msg2[4*1024*8*32];
__device__ float  g_fin1[4*4096*8*32];
__device__ int    g_idx2[4*8*1024*16];
__device__ int    g_idx1[4*8*4096*8];

__device__ __forceinline__ unsigned ford(float f) {
    unsigned u = __float_as_uint(f);
    return (u & 0x80000000u) ? ~u : (u | 0x80000000u);
}
__device__ __forceinline__ unsigned long long ffma2(unsigned long long a,
                                                    unsigned long long b,
                                                    unsigned long long c) {
    unsigned long long d;
    asm("fma.rn.f32x2 %0, %1, %2, %3;" : "=l"(d) : "l"(a), "l"(b), "l"(c));
    return d;
}
__device__ __forceinline__ unsigned long long addf2(unsigned long long a,
                                                    unsigned long long b) {
    unsigned long long d;
    asm("add.rn.f32x2 %0, %1, %2;" : "=l"(d) : "l"(a), "l"(b));
    return d;
}
__device__ __forceinline__ float2 u2f2(unsigned long long a) {
    float2 r;
    asm("mov.b64 {%0, %1}, %2;" : "=f"(r.x), "=f"(r.y) : "l"(a));
    return r;
}
__device__ __forceinline__ unsigned long long f2u2(float x, float y) {
    unsigned long long r;
    asm("mov.b64 %0, {%1, %2};" : "=l"(r) : "f"(x), "f"(y));
    return r;
}
__device__ __forceinline__ void h8_to_f8(uint4 r, float4* lo, float4* hi) {
    __half2 h0 = *(__half2*)&r.x, h1 = *(__half2*)&r.y;
    __half2 h2 = *(__half2*)&r.z, h3 = *(__half2*)&r.w;
    float2 f0 = __half22float2(h0), f1 = __half22float2(h1);
    float2 f2 = __half22float2(h2), f3 = __half22float2(h3);
    *lo = make_float4(f0.x, f0.y, f1.x, f1.y);
    *hi = make_float4(f2.x, f2.y, f3.x, f3.y);
}
// per-thread 16B async copy global->shared (no registers, coalescing-friendly)
__device__ __forceinline__ void cp16(void* smem_dst, const void* gsrc) {
    unsigned sa = (unsigned)__cvta_generic_to_shared(smem_dst);
    asm volatile("cp.async.cg.shared.global [%0], [%1], 16;\n" :: "r"(sa), "l"(gsrc));
}
#define CP_COMMIT() asm volatile("cp.async.commit_group;\n")
#define CP_WAIT0()  asm volatile("cp.async.wait_group 0;\n")

// ---- float4 transpose (b,256,S) -> (b,S,256); fp16 out for k0,v0,v1 ------
__global__ void __launch_bounds__(256) tr_fast(const float* __restrict__ q,
                                               const float* __restrict__ k,
                                               const float* __restrict__ v, int S) {
    __shared__ float sm[32][132];
    const int which = blockIdx.z >> 2, b = blockIdx.z & 3;
    const float* in = which == 0 ? q : which == 1 ? k : v;
    float* outf = 0; __half* outh = 0;
    if (S == 16384) {
        if (which == 0) outf = g_q0t;
        else if (which == 1) outh = g_k0h;
        else outh = g_v0h;
    } else if (S == 4096) {
        if (which == 0) outf = g_q1t;
        else if (which == 1) outf = g_k1t;
        else outh = g_v1h;
    } else {
        outf = which == 0 ? g_q2t : which == 1 ? g_k2t : g_v2t;
    }
    const int s0 = blockIdx.x * 128, c0 = blockIdx.y * 32;
    const int tid = threadIdx.x, tx = tid & 31, ty = tid >> 5;
    const float* ib = in + (size_t)b * 256 * S;
#pragma unroll
    for (int kk = 0; kk < 4; kk++) {
        int c = ty + 8 * kk;
        *(float4*)&sm[c][4 * tx] = *(const float4*)(ib + (size_t)(c0 + c) * S + s0 + 4 * tx);
    }
    __syncthreads();
    if (outh) {
        __half* ob = outh + (size_t)b * 256 * S;
#pragma unroll
        for (int m = 0; m < 4; m++) {
            int j = tid + 256 * m, sl = j >> 3, cf = j & 7;
            __half2 h0 = __floats2half2_rn(sm[4 * cf][sl], sm[4 * cf + 1][sl]);
            __half2 h1 = __floats2half2_rn(sm[4 * cf + 2][sl], sm[4 * cf + 3][sl]);
            uint2 st;
            st.x = *(unsigned*)&h0; st.y = *(unsigned*)&h1;
            *(uint2*)(ob + (size_t)(s0 + sl) * 256 + c0 + 4 * cf) = st;
        }
    } else {
        float* ob = outf + (size_t)b * 256 * S;
#pragma unroll
        for (int m = 0; m < 4; m++) {
            int j = tid + 256 * m, sl = j >> 3, cf = j & 7;
            float4 o = make_float4(sm[4 * cf][sl], sm[4 * cf + 1][sl],
                                   sm[4 * cf + 2][sl], sm[4 * cf + 3][sl]);
            *(float4*)(ob + (size_t)(s0 + sl) * 256 + c0 + 4 * cf) = o;
        }
    }
}

// ---- coarse: 2 q/warp, f32x2, 128-key tiles, cp.async double buffer ------
#define CP_STAGE(GBASE, SMEMT, TID)                                            \
    {                                                                          \
        _Pragma("unroll") for (int it_ = 0; it_ < 4; it_++) {                  \
            int i_ = (TID) + it_ * 256, key_ = i_ >> 3, f_ = i_ & 7;           \
            cp16((SMEMT) + (key_ * 36 + f_ * 4) * 4,                           \
                 (GBASE) + (size_t)key_ * 256 + f_ * 4);                       \
        }                                                                      \
        CP_COMMIT();                                                           \
    }

__global__ void __launch_bounds__(256) coarse_kernel() {
    extern __shared__ __align__(16) char smem_raw[];
    float* As = (float*)smem_raw;  // [16][1024]
    const int head = blockIdx.y, b = blockIdx.z;
    const int tid = threadIdx.x, w = tid >> 5, lane = tid & 31;
    const int l0 = blockIdx.x * 16 + 2 * w;
    float* As0 = As + (2 * w) * 1024;
    float* As1 = As0 + 1024;
    char* tileA = smem_raw + 65536;
    char* tileB = tileA + 18432;

    const float* ktb = g_k2t + (size_t)b * 1024 * 256 + head * 32;
    const float* vtb = g_v2t + (size_t)b * 1024 * 256 + head * 32;

    // ---- pass 1: logits into As -----------------------------------------
    {
        unsigned long long q0[16], q1[16];
        const float* qp = g_q2t + ((size_t)(b * 1024 + l0)) * 256 + head * 32;
#pragma unroll
        for (int r = 0; r < 16; r++) {
            q0[r] = *(const unsigned long long*)(qp + 2 * r);
            q1[r] = *(const unsigned long long*)(qp + 256 + 2 * r);
        }
        CP_STAGE(ktb, tileA, tid);
#pragma unroll
        for (int t = 0; t < 8; t++) {
            char* cur = (t & 1) ? tileB : tileA;
            char* nxt = (t & 1) ? tileA : tileB;
            if (t < 7) {
                CP_STAGE(ktb + (size_t)(t + 1) * 128 * 256, nxt, tid);
                asm volatile("cp.async.wait_group 1;\n");
            } else {
                asm volatile("cp.async.wait_group 0;\n");
            }
            __syncthreads();
            const float (*ks)[36] = (const float(*)[36])cur;
#pragma unroll
            for (int j = 0; j < 4; j++) {
                int key = j * 32 + lane;
                const ulonglong2* kr = (const ulonglong2*)&ks[key][0];
                unsigned long long a0 = 0ull, a1 = 0ull;
#pragma unroll
                for (int r = 0; r < 8; r++) {
                    ulonglong2 kk = kr[r];
                    a0 = ffma2(q0[2 * r], kk.x, a0);
                    a0 = ffma2(q0[2 * r + 1], kk.y, a0);
                    a1 = ffma2(q1[2 * r], kk.x, a1);
                    a1 = ffma2(q1[2 * r + 1], kk.y, a1);
                }
                float2 f0 = u2f2(a0), f1 = u2f2(a1);
                As0[t * 128 + key] = f0.x + f0.y;
                As1[t * 128 + key] = f1.x + f1.y;
            }
            __syncthreads();
        }
    }

    // prefetch first V tile behind the topk/softmax phase
    CP_STAGE(vtb, tileA, tid);

    // ---- top-16 (raw logits; only the SET matters) + softmax -------------
    for (int qi = 0; qi < 2; qi++) {
        float* Aq = qi ? As1 : As0;
        float sc[32];
#pragma unroll
        for (int i = 0; i < 32; i++) sc[i] = Aq[i * 32 + lane];
        unsigned c1 = 0u, c2 = 0u; int i1 = 0, i2 = 0;
#pragma unroll
        for (int i = 0; i < 32; i++) {
            unsigned v = ford(sc[i]);
            if (v > c1) { c2 = c1; i2 = i1; c1 = v; i1 = i; }
            else if (v > c2) { c2 = v; i2 = i; }
        }
        int myidx = 0;
        for (int r = 0; r < 16; r++) {
            unsigned wm = __reduce_max_sync(FM, c1);
            unsigned ball = __ballot_sync(FM, c1 == wm);
            int src = __ffs(ball) - 1;
            int sli = __shfl_sync(FM, i1, src);
            if (lane == r) myidx = sli * 32 + src;
            if (lane == src) {
                if (c2 == 0u) {
                    unsigned a = 0u, bq = 0u; int ai = 0, bi = 0;
#pragma unroll
                    for (int i = 0; i < 32; i++) {
                        unsigned v = ford(sc[i]);
                        if (v < wm) {
                            if (v > a) { bq = a; bi = ai; a = v; ai = i; }
                            else if (v > bq) { bq = v; bi = i; }
                        }
                    }
                    c1 = a; i1 = ai; c2 = bq; i2 = bi;
                } else {
                    c1 = c2; i1 = i2; c2 = 0u;
                }
            }
        }
        if (lane < 16)
            g_idx2[((size_t)(b * 8 + head) * 1024 + l0 + qi) * 16 + lane] = myidx;
        float m = sc[0];
#pragma unroll
        for (int i = 1; i < 32; i++) m = fmaxf(m, sc[i]);
#pragma unroll
        for (int o = 16; o; o >>= 1) m = fmaxf(m, __shfl_xor_sync(FM, m, o));
        float sum = 0.f;
#pragma unroll
        for (int i = 0; i < 32; i++) { sc[i] = __expf((sc[i] - m) * SCALE_D); sum += sc[i]; }
#pragma unroll
        for (int o = 16; o; o >>= 1) sum += __shfl_xor_sync(FM, sum, o);
        float inv = 1.f / sum;
#pragma unroll
        for (int i = 0; i < 32; i++) Aq[i * 32 + lane] = sc[i] * inv;
    }

    // ---- pass 2: A @ V (packed, double buffered) -------------------------
    unsigned long long m0[16], m1[16];
#pragma unroll
    for (int r = 0; r < 16; r++) { m0[r] = 0ull; m1[r] = 0ull; }
#pragma unroll
    for (int t = 0; t < 8; t++) {
        char* cur = (t & 1) ? tileB : tileA;
        char* nxt = (t & 1) ? tileA : tileB;
        if (t < 7) {
            CP_STAGE(vtb + (size_t)(t + 1) * 128 * 256, nxt, tid);
            asm volatile("cp.async.wait_group 1;\n");
        } else {
            asm volatile("cp.async.wait_group 0;\n");
        }
        __syncthreads();
        const float (*ks)[36] = (const float(*)[36])cur;
#pragma unroll
        for (int j = 0; j < 4; j++) {
            int key = j * 32 + lane, gk = t * 128 + key;
            float a0s = As0[gk], a1s = As1[gk];
            unsigned long long a0 = f2u2(a0s, a0s), a1 = f2u2(a1s, a1s);
            const ulonglong2* vr = (const ulonglong2*)&ks[key][0];
#pragma unroll
            for (int r = 0; r < 8; r++) {
                ulonglong2 vv = vr[r];
                m0[2 * r]     = ffma2(a0, vv.x, m0[2 * r]);
                m0[2 * r + 1] = ffma2(a0, vv.y, m0[2 * r + 1]);
                m1[2 * r]     = ffma2(a1, vv.x, m1[2 * r]);
                m1[2 * r + 1] = ffma2(a1, vv.y, m1[2 * r + 1]);
            }
        }
        __syncthreads();
    }
#define RSU(M, OFF, HALF) { int bit = (lane & OFF) ? 1 : 0;                   \
    _Pragma("unroll") for (int r = 0; r < HALF; r++) {                        \
        unsigned long long lo = M[r], hi = M[HALF + r];                       \
        unsigned long long snd = bit ? lo : hi;                               \
        unsigned long long rcv = __shfl_xor_sync(FM, snd, OFF);               \
        M[r] = addf2(bit ? hi : lo, rcv); } }
#pragma unroll
    for (int qi = 0; qi < 2; qi++) {
        unsigned long long* M = qi ? m1 : m0;
        RSU(M, 16, 8) RSU(M, 8, 4) RSU(M, 4, 2) RSU(M, 2, 1)
        float2 f2 = u2f2(M[0]);
        float snd = (lane & 1) ? f2.x : f2.y;
        float rcv = __shfl_xor_sync(FM, snd, 1);
        float val = ((lane & 1) ? f2.y : f2.x) + rcv;
        g_msg2[((size_t)(b * 1024 + l0 + qi) * 8 + head) * 32 + lane] = val;
    }
#undef RSU
}

// ---- fine level 1: cooperative K gather (fp32 smem), V reuses K buffer ---
__global__ void __launch_bounds__(128) fine1_kernel(const float* __restrict__ wt) {
    __shared__ __align__(16) float kvs[4][64][36];  // K fp32, later V fp16 overlay
    __shared__ __align__(16) float aw[4][64][4];
    __shared__ __align__(16) float qw[4][4][32];
    const int tid = threadIdx.x, w = tid >> 5, lane = tid & 31;
    const int g = blockIdx.x*4 + w;
    const int b = g >> 13, r = g & 8191, h = r >> 10, l2 = r & 1023;
    const int r2 = l2 >> 5, c2 = l2 & 31;

    float w0 = wt[0], w1 = wt[1], w2 = wt[2];
    float wmx = fmaxf(w0, fmaxf(w1, w2));
    float e0 = __expf(w0-wmx), e1 = __expf(w1-wmx), e2 = __expf(w2-wmx);
    float ws0 = e0/(e0+e1+e2), ws1 = e1/(e0+e1+e2);

    int pid = g_idx2[((size_t)(b*8+h)*1024 + l2)*16 + (lane & 15)];
    int p0 = __shfl_sync(FM, pid, lane >> 2);
    int p1 = __shfl_sync(FM, pid, 8 + (lane >> 2));
    int cx = (lane >> 1) & 1, cy = lane & 1;
    int gid0 = (2*(p0>>5)+cx)*64 + 2*(p0&31)+cy;
    int gid1 = (2*(p1>>5)+cx)*64 + 2*(p1&31)+cy;

    const float*  kb  = g_k1t + (size_t)b*4096*256 + h*32;
    const __half* vbh = g_v1h + (size_t)b*4096*256 + h*32;

    // cooperative K gather: 8 lanes per key, 16B chunks
    {
        int sub = lane >> 3, c = lane & 7;
#pragma unroll
        for (int i = 0; i < 16; i++) {
            int K = 4*i + sub;
            int gk = (i < 8) ? __shfl_sync(FM, gid0, K & 31)
                             : __shfl_sync(FM, gid1, K & 31);
            cp16(&kvs[w][K][c*4], kb + (size_t)gk*256 + c*4);
        }
        CP_COMMIT();
    }
    { int t = lane >> 3, f = (lane & 7)*4;
      int qpos = (2*r2 + (t>>1))*64 + 2*c2 + (t&1);
      *(float4*)&qw[w][t][f] = *(const float4*)(g_q1t + ((size_t)(b*4096+qpos))*256 + h*32 + f); }
    CP_WAIT0();
    __syncwarp();

    float4 k0[8], k1[8];
    {
        const float4* kp0 = (const float4*)&kvs[w][lane][0];
        const float4* kp1 = (const float4*)&kvs[w][lane+32][0];
#pragma unroll
        for (int f = 0; f < 8; f++) { k0[f] = kp0[f]; k1[f] = kp1[f]; }
    }
    __syncwarp();  // K register-resident; safe to overwrite buffer with V

    __half* vh = (__half*)&kvs[w][0][0];  // overlay: [64][40] halves
    {
        int sub = lane >> 2, c = lane & 3;
#pragma unroll
        for (int i = 0; i < 8; i++) {
            int K = 8*i + sub;
            int gk = (i < 4) ? __shfl_sync(FM, gid0, K & 31)
                             : __shfl_sync(FM, gid1, K & 31);
            cp16(vh + K*40 + c*8, vbh + (size_t)gk*256 + c*8);
        }
        CP_COMMIT();
    }

    float lg[2][4];
#pragma unroll
    for (int t = 0; t < 4; t++) {
        float a0 = 0.f, a1 = 0.f;
#pragma unroll
        for (int f = 0; f < 8; f++) {
            float4 qf = *(float4*)&qw[w][t][f*4];
            a0 += qf.x*k0[f].x + qf.y*k0[f].y + qf.z*k0[f].z + qf.w*k0[f].w;
            a1 += qf.x*k1[f].x + qf.y*k1[f].y + qf.z*k1[f].z + qf.w*k1[f].w;
        }
        lg[0][t] = a0*SCALE_D; lg[1][t] = a1*SCALE_D;
    }
    float av0[4], av1[4];
#pragma unroll
    for (int t = 0; t < 4; t++) {
        float m = fmaxf(lg[0][t], lg[1][t]);
#pragma unroll
        for (int o = 16; o; o >>= 1) m = fmaxf(m, __shfl_xor_sync(FM, m, o));
        float x0 = __expf(lg[0][t]-m), x1 = __expf(lg[1][t]-m);
        float s = x0 + x1;
#pragma unroll
        for (int o = 16; o; o >>= 1) s += __shfl_xor_sync(FM, s, o);
        av0[t] = x0/s; av1[t] = x1/s;
    }
    *(float4*)&aw[w][lane][0]    = make_float4(av0[0], av0[1], av0[2], av0[3]);
    *(float4*)&aw[w][lane+32][0] = make_float4(av1[0], av1[1], av1[2], av1[3]);

#pragma unroll
    for (int t = 0; t < 4; t++) {
        unsigned o0 = ford(lg[0][t]), o1 = ford(lg[1][t]);
        int keep = 0;
        for (int rr = 0; rr < 8; rr++) {
            unsigned lmx = max(o0, o1);
            unsigned wm = __reduce_max_sync(FM, lmx);
            unsigned ball = __ballot_sync(FM, lmx == wm);
            int src = __ffs(ball) - 1;
            int mysel = (o1 > o0) ? gid1 : gid0;
            int gsel = __shfl_sync(FM, mysel, src);
            if (lane == rr) keep = gsel;
            if (lane == src) { if (o1 > o0) o1 = 0u; else o0 = 0u; }
        }
        int qpos = (2*r2 + (t>>1))*64 + 2*c2 + (t&1);
        if (lane < 8) g_idx1[((size_t)(b*8+h)*4096 + qpos)*8 + lane] = keep;
    }
    CP_WAIT0();
    __syncwarp();
    float acc[4] = {0.f, 0.f, 0.f, 0.f};
#pragma unroll 8
    for (int k = 0; k < 64; k++) {
        float v = __half2float(vh[k * 40 + lane]);
        float4 a4 = *(float4*)&aw[w][k][0];
        acc[0] += a4.x*v; acc[1] += a4.y*v; acc[2] += a4.z*v; acc[3] += a4.w*v;
    }
    float m2 = g_msg2[((size_t)(b*1024+l2)*8 + h)*32 + lane] * ws0;
#pragma unroll
    for (int t = 0; t < 4; t++) {
        int qpos = (2*r2 + (t>>1))*64 + 2*c2 + (t&1);
        g_fin1[((size_t)(b*4096+qpos)*8 + h)*32 + lane] = m2 + acc[t]*ws1;
    }
}

// ---- fine level 0: cooperative fp16 K+V gather via cp.async --------------
// dynamic smem: ksh[8][32][40]h | vsh[8][32][40]h | aw[8][32][4]f | qw[8][4][32]f
__global__ void __launch_bounds__(256) fine0_kernel(const float* __restrict__ wt,
                                                    float* __restrict__ out) {
    extern __shared__ __align__(16) char f0smem[];
    const int tid = threadIdx.x, w = tid >> 5, lane = tid & 31;
    __half* ksh = (__half*)(f0smem + w * 2560);
    __half* vsh = (__half*)(f0smem + 20480 + w * 2560);
    float (*aw)[4] = (float(*)[4])(f0smem + 40960 + w * 512);
    float (*qw)[32] = (float(*)[32])(f0smem + 45056 + w * 512);
    const int g = blockIdx.x*8 + w;
    const int b = g >> 15, r = g & 32767, h = r >> 12, l1 = r & 4095;
    const int R = l1 >> 6, C = l1 & 63;

    float w0 = wt[0], w1 = wt[1], w2 = wt[2];
    float wmx = fmaxf(w0, fmaxf(w1, w2));
    float e0 = __expf(w0-wmx), e1 = __expf(w1-wmx), e2 = __expf(w2-wmx);
    float ws2 = e2/(e0+e1+e2);

    int p = g_idx1[((size_t)(b*8+h)*4096 + l1)*8 + (lane >> 2)];
    int cx = (lane >> 1) & 1, cy = lane & 1;
    int gid = (2*(p>>6)+cx)*128 + 2*(p&63)+cy;

    const __half* kbh = g_k0h + (size_t)b*16384*256 + h*32;
    const __half* vbh = g_v0h + (size_t)b*16384*256 + h*32;

    // cooperative K+V gather: 4 lanes per key, 16B chunks
    {
        int sub = lane >> 2, c = lane & 3;
#pragma unroll
        for (int i = 0; i < 4; i++) {
            int K = 8*i + sub;
            int gk = __shfl_sync(FM, gid, K);
            cp16(ksh + K*40 + c*8, kbh + (size_t)gk*256 + c*8);
            cp16(vsh + K*40 + c*8, vbh + (size_t)gk*256 + c*8);
        }
        CP_COMMIT();
    }
    { int t = lane >> 3, f = (lane & 7)*4;
      int qpos = (2*R + (t>>1))*128 + 2*C + (t&1);
      *(float4*)&qw[t][f] = *(const float4*)(g_q0t + ((size_t)(b*16384+qpos))*256 + h*32 + f); }
    CP_WAIT0();
    __syncwarp();

    float4 kr[8];
    {
        const uint4* kp = (const uint4*)(ksh + lane*40);
#pragma unroll
        for (int f = 0; f < 4; f++) h8_to_f8(kp[f], &kr[2*f], &kr[2*f+1]);
    }

    float lg[4];
#pragma unroll
    for (int t = 0; t < 4; t++) {
        float a = 0.f;
#pragma unroll
        for (int f = 0; f < 8; f++) {
            float4 qf = *(float4*)&qw[t][f*4];
            a += qf.x*kr[f].x + qf.y*kr[f].y + qf.z*kr[f].z + qf.w*kr[f].w;
        }
        lg[t] = a*SCALE_D;
    }
    float av[4];
#pragma unroll
    for (int t = 0; t < 4; t++) {
        float m = lg[t];
#pragma unroll
        for (int o = 16; o; o >>= 1) m = fmaxf(m, __shfl_xor_sync(FM, m, o));
        float x = __expf(lg[t]-m);
        float s = x;
#pragma unroll
        for (int o = 16; o; o >>= 1) s += __shfl_xor_sync(FM, s, o);
        av[t] = x/s;
    }
    *(float4*)&aw[lane][0] = make_float4(av[0], av[1], av[2], av[3]);
    __syncwarp();
    float acc[4] = {0.f, 0.f, 0.f, 0.f};
#pragma unroll 8
    for (int k = 0; k < 32; k++) {
        float v = __half2float(vsh[k * 40 + lane]);
        float4 a4 = *(float4*)&aw[k][0];
        acc[0] += a4.x*v; acc[1] += a4.y*v; acc[2] += a4.z*v; acc[3] += a4.w*v;
    }
    float base = g_fin1[((size_t)(b*4096+l1)*8 + h)*32 + lane];
#pragma unroll
    for (int t = 0; t < 4; t++) {
        int qpos = (2*R + (t>>1))*128 + 2*C + (t&1);
        out[((size_t)(b*16384+qpos)*8 + h)*32 + lane] = base + acc[t]*ws2;
    }
}

extern "C" void kernel_launch(void* const* d_in, const int* in_sizes, int n_in,
                              void* d_out, int out_size) {
    const float* q0 = (const float*)d_in[0];
    const float* q1 = (const float*)d_in[1];
    const float* q2 = (const float*)d_in[2];
    const float* k0 = (const float*)d_in[3];
    const float* k1 = (const float*)d_in[4];
    const float* k2 = (const float*)d_in[5];
    const float* v0 = (const float*)d_in[6];
    const float* v1 = (const float*)d_in[7];
    const float* v2 = (const float*)d_in[8];
    const float* wt = (const float*)d_in[9];
    static int smem_set = 0;
    if (!smem_set) {
        cudaFuncSetAttribute(coarse_kernel,
                             cudaFuncAttributeMaxDynamicSharedMemorySize, 102400);
        cudaFuncSetAttribute(fine0_kernel,
                             cudaFuncAttributeMaxDynamicSharedMemorySize, 49152);
        smem_set = 1;
    }
    tr_fast<<<dim3(128, 8, 12), 256>>>(q0, k0, v0, 16384);
    tr_fast<<<dim3(32, 8, 12), 256>>>(q1, k1, v1, 4096);
    tr_fast<<<dim3(8, 8, 12), 256>>>(q2, k2, v2, 1024);
    coarse_kernel<<<dim3(64, 8, 4), 256, 102400>>>();
    fine1_kernel<<<8192, 128>>>(wt);
    fine0_kernel<<<16384, 256, 49152>>>(wt, (float*)d_out);
}

// round 15
// speedup vs baseline: 2.1122x; 1.0049x over previous
#include <cuda_runtime.h>
#include <cuda_fp16.h>

#define FM 0xffffffffu
#define SCALE_D 0.17677669529663688f  // 1/sqrt(32)

// ---- scratch (device globals; allocation is forbidden) ----
__device__ float  g_q0t[4*16384*256];
__device__ __half g_k0h[4*16384*256];
__device__ __half g_v0h[4*16384*256];
__device__ float  g_q1t[4*4096*256];
__device__ float  g_k1t[4*4096*256];
__device__ __half g_v1h[4*4096*256];
__device__ float  g_q2t[4*1024*256];
__device__ float  g_k2t[4*1024*256];
__device__ float  g_v2t[4*1024*256];
__device__ float  g_msg2[4*1024*8*32];
__device__ float  g_fin1[4*4096*8*32];
__device__ int    g_idx2[4*8*1024*16];
__device__ int    g_idx1[4*8*4096*8];

__device__ __forceinline__ unsigned ford(float f) {
    unsigned u = __float_as_uint(f);
    return (u & 0x80000000u) ? ~u : (u | 0x80000000u);
}
__device__ __forceinline__ unsigned long long ffma2(unsigned long long a,
                                                    unsigned long long b,
                                                    unsigned long long c) {
    unsigned long long d;
    asm("fma.rn.f32x2 %0, %1, %2, %3;" : "=l"(d) : "l"(a), "l"(b), "l"(c));
    return d;
}
__device__ __forceinline__ unsigned long long addf2(unsigned long long a,
                                                    unsigned long long b) {
    unsigned long long d;
    asm("add.rn.f32x2 %0, %1, %2;" : "=l"(d) : "l"(a), "l"(b));
    return d;
}
__device__ __forceinline__ float2 u2f2(unsigned long long a) {
    float2 r;
    asm("mov.b64 {%0, %1}, %2;" : "=f"(r.x), "=f"(r.y) : "l"(a));
    return r;
}
__device__ __forceinline__ unsigned long long f2u2(float x, float y) {
    unsigned long long r;
    asm("mov.b64 %0, {%1, %2};" : "=l"(r) : "f"(x), "f"(y));
    return r;
}
__device__ __forceinline__ void h8_to_f8(uint4 r, float4* lo, float4* hi) {
    __half2 h0 = *(__half2*)&r.x, h1 = *(__half2*)&r.y;
    __half2 h2 = *(__half2*)&r.z, h3 = *(__half2*)&r.w;
    float2 f0 = __half22float2(h0), f1 = __half22float2(h1);
    float2 f2 = __half22float2(h2), f3 = __half22float2(h3);
    *lo = make_float4(f0.x, f0.y, f1.x, f1.y);
    *hi = make_float4(f2.x, f2.y, f3.x, f3.y);
}
__device__ __forceinline__ void cp16(void* smem_dst, const void* gsrc) {
    unsigned sa = (unsigned)__cvta_generic_to_shared(smem_dst);
    asm volatile("cp.async.cg.shared.global [%0], [%1], 16;\n" :: "r"(sa), "l"(gsrc));
}
#define CP_COMMIT() asm volatile("cp.async.commit_group;\n")
#define CP_WAIT0()  asm volatile("cp.async.wait_group 0;\n")

// ---- float4 transpose (b,256,S) -> (b,S,256); fp16 out for k0,v0,v1 ------
__global__ void __launch_bounds__(256) tr_fast(const float* __restrict__ q,
                                               const float* __restrict__ k,
                                               const float* __restrict__ v, int S) {
    __shared__ float sm[32][132];
    const int which = blockIdx.z >> 2, b = blockIdx.z & 3;
    const float* in = which == 0 ? q : which == 1 ? k : v;
    float* outf = 0; __half* outh = 0;
    if (S == 16384) {
        if (which == 0) outf = g_q0t;
        else if (which == 1) outh = g_k0h;
        else outh = g_v0h;
    } else if (S == 4096) {
        if (which == 0) outf = g_q1t;
        else if (which == 1) outf = g_k1t;
        else outh = g_v1h;
    } else {
        outf = which == 0 ? g_q2t : which == 1 ? g_k2t : g_v2t;
    }
    const int s0 = blockIdx.x * 128, c0 = blockIdx.y * 32;
    const int tid = threadIdx.x, tx = tid & 31, ty = tid >> 5;
    const float* ib = in + (size_t)b * 256 * S;
#pragma unroll
    for (int kk = 0; kk < 4; kk++) {
        int c = ty + 8 * kk;
        *(float4*)&sm[c][4 * tx] = *(const float4*)(ib + (size_t)(c0 + c) * S + s0 + 4 * tx);
    }
    __syncthreads();
    if (outh) {
        __half* ob = outh + (size_t)b * 256 * S;
#pragma unroll
        for (int m = 0; m < 4; m++) {
            int j = tid + 256 * m, sl = j >> 3, cf = j & 7;
            __half2 h0 = __floats2half2_rn(sm[4 * cf][sl], sm[4 * cf + 1][sl]);
            __half2 h1 = __floats2half2_rn(sm[4 * cf + 2][sl], sm[4 * cf + 3][sl]);
            uint2 st;
            st.x = *(unsigned*)&h0; st.y = *(unsigned*)&h1;
            *(uint2*)(ob + (size_t)(s0 + sl) * 256 + c0 + 4 * cf) = st;
        }
    } else {
        float* ob = outf + (size_t)b * 256 * S;
#pragma unroll
        for (int m = 0; m < 4; m++) {
            int j = tid + 256 * m, sl = j >> 3, cf = j & 7;
            float4 o = make_float4(sm[4 * cf][sl], sm[4 * cf + 1][sl],
                                   sm[4 * cf + 2][sl], sm[4 * cf + 3][sl]);
            *(float4*)(ob + (size_t)(s0 + sl) * 256 + c0 + 4 * cf) = o;
        }
    }
}

// ---- coarse: 2 q/warp, f32x2, 128-key tiles, cp.async double buffer ------
#define CP_STAGE(GBASE, SMEMT, TID)                                            \
    {                                                                          \
        _Pragma("unroll") for (int it_ = 0; it_ < 4; it_++) {                  \
            int i_ = (TID) + it_ * 256, key_ = i_ >> 3, f_ = i_ & 7;           \
            cp16((SMEMT) + (key_ * 36 + f_ * 4) * 4,                           \
                 (GBASE) + (size_t)key_ * 256 + f_ * 4);                       \
        }                                                                      \
        CP_COMMIT();                                                           \
    }

__global__ void __launch_bounds__(256) coarse_kernel() {
    extern __shared__ __align__(16) char smem_raw[];
    float* As = (float*)smem_raw;  // [16][1024]
    const int head = blockIdx.y, b = blockIdx.z;
    const int tid = threadIdx.x, w = tid >> 5, lane = tid & 31;
    const int l0 = blockIdx.x * 16 + 2 * w;
    float* As0 = As + (2 * w) * 1024;
    float* As1 = As0 + 1024;
    char* tileA = smem_raw + 65536;
    char* tileB = tileA + 18432;

    const float* ktb = g_k2t + (size_t)b * 1024 * 256 + head * 32;
    const float* vtb = g_v2t + (size_t)b * 1024 * 256 + head * 32;

    // ---- pass 1: logits into As -----------------------------------------
    {
        unsigned long long q0[16], q1[16];
        const float* qp = g_q2t + ((size_t)(b * 1024 + l0)) * 256 + head * 32;
#pragma unroll
        for (int r = 0; r < 16; r++) {
            q0[r] = *(const unsigned long long*)(qp + 2 * r);
            q1[r] = *(const unsigned long long*)(qp + 256 + 2 * r);
        }
        CP_STAGE(ktb, tileA, tid);
#pragma unroll
        for (int t = 0; t < 8; t++) {
            char* cur = (t & 1) ? tileB : tileA;
            char* nxt = (t & 1) ? tileA : tileB;
            if (t < 7) {
                CP_STAGE(ktb + (size_t)(t + 1) * 128 * 256, nxt, tid);
                asm volatile("cp.async.wait_group 1;\n");
            } else {
                asm volatile("cp.async.wait_group 0;\n");
            }
            __syncthreads();
            const float (*ks)[36] = (const float(*)[36])cur;
#pragma unroll
            for (int j = 0; j < 4; j++) {
                int key = j * 32 + lane;
                const ulonglong2* kr = (const ulonglong2*)&ks[key][0];
                unsigned long long a0 = 0ull, a1 = 0ull;
#pragma unroll
                for (int r = 0; r < 8; r++) {
                    ulonglong2 kk = kr[r];
                    a0 = ffma2(q0[2 * r], kk.x, a0);
                    a0 = ffma2(q0[2 * r + 1], kk.y, a0);
                    a1 = ffma2(q1[2 * r], kk.x, a1);
                    a1 = ffma2(q1[2 * r + 1], kk.y, a1);
                }
                float2 f0 = u2f2(a0), f1 = u2f2(a1);
                As0[t * 128 + key] = f0.x + f0.y;
                As1[t * 128 + key] = f1.x + f1.y;
            }
            __syncthreads();
        }
    }

    // prefetch first V tile behind the topk/softmax phase
    CP_STAGE(vtb, tileA, tid);

    // ---- top-16 (raw logits; only the SET matters) + softmax -------------
    for (int qi = 0; qi < 2; qi++) {
        float* Aq = qi ? As1 : As0;
        float sc[32];
#pragma unroll
        for (int i = 0; i < 32; i++) sc[i] = Aq[i * 32 + lane];
        unsigned c1 = 0u, c2 = 0u; int i1 = 0, i2 = 0;
#pragma unroll
        for (int i = 0; i < 32; i++) {
            unsigned v = ford(sc[i]);
            if (v > c1) { c2 = c1; i2 = i1; c1 = v; i1 = i; }
            else if (v > c2) { c2 = v; i2 = i; }
        }
        int myidx = 0;
        for (int r = 0; r < 16; r++) {
            unsigned wm = __reduce_max_sync(FM, c1);
            unsigned ball = __ballot_sync(FM, c1 == wm);
            int src = __ffs(ball) - 1;
            int sli = __shfl_sync(FM, i1, src);
            if (lane == r) myidx = sli * 32 + src;
            if (lane == src) {
                if (c2 == 0u) {
                    unsigned a = 0u, bq = 0u; int ai = 0, bi = 0;
#pragma unroll
                    for (int i = 0; i < 32; i++) {
                        unsigned v = ford(sc[i]);
                        if (v < wm) {
                            if (v > a) { bq = a; bi = ai; a = v; ai = i; }
                            else if (v > bq) { bq = v; bi = i; }
                        }
                    }
                    c1 = a; i1 = ai; c2 = bq; i2 = bi;
                } else {
                    c1 = c2; i1 = i2; c2 = 0u;
                }
            }
        }
        if (lane < 16)
            g_idx2[((size_t)(b * 8 + head) * 1024 + l0 + qi) * 16 + lane] = myidx;
        float m = sc[0];
#pragma unroll
        for (int i = 1; i < 32; i++) m = fmaxf(m, sc[i]);
#pragma unroll
        for (int o = 16; o; o >>= 1) m = fmaxf(m, __shfl_xor_sync(FM, m, o));
        float sum = 0.f;
#pragma unroll
        for (int i = 0; i < 32; i++) { sc[i] = __expf((sc[i] - m) * SCALE_D); sum += sc[i]; }
#pragma unroll
        for (int o = 16; o; o >>= 1) sum += __shfl_xor_sync(FM, sum, o);
        float inv = 1.f / sum;
#pragma unroll
        for (int i = 0; i < 32; i++) Aq[i * 32 + lane] = sc[i] * inv;
    }

    // ---- pass 2: A @ V (packed, double buffered) -------------------------
    unsigned long long m0[16], m1[16];
#pragma unroll
    for (int r = 0; r < 16; r++) { m0[r] = 0ull; m1[r] = 0ull; }
#pragma unroll
    for (int t = 0; t < 8; t++) {
        char* cur = (t & 1) ? tileB : tileA;
        char* nxt = (t & 1) ? tileA : tileB;
        if (t < 7) {
            CP_STAGE(vtb + (size_t)(t + 1) * 128 * 256, nxt, tid);
            asm volatile("cp.async.wait_group 1;\n");
        } else {
            asm volatile("cp.async.wait_group 0;\n");
        }
        __syncthreads();
        const float (*ks)[36] = (const float(*)[36])cur;
#pragma unroll
        for (int j = 0; j < 4; j++) {
            int key = j * 32 + lane, gk = t * 128 + key;
            float a0s = As0[gk], a1s = As1[gk];
            unsigned long long a0 = f2u2(a0s, a0s), a1 = f2u2(a1s, a1s);
            const ulonglong2* vr = (const ulonglong2*)&ks[key][0];
#pragma unroll
            for (int r = 0; r < 8; r++) {
                ulonglong2 vv = vr[r];
                m0[2 * r]     = ffma2(a0, vv.x, m0[2 * r]);
                m0[2 * r + 1] = ffma2(a0, vv.y, m0[2 * r + 1]);
                m1[2 * r]     = ffma2(a1, vv.x, m1[2 * r]);
                m1[2 * r + 1] = ffma2(a1, vv.y, m1[2 * r + 1]);
            }
        }
        __syncthreads();
    }
#define RSU(M, OFF, HALF) { int bit = (lane & OFF) ? 1 : 0;                   \
    _Pragma("unroll") for (int r = 0; r < HALF; r++) {                        \
        unsigned long long lo = M[r], hi = M[HALF + r];                       \
        unsigned long long snd = bit ? lo : hi;                               \
        unsigned long long rcv = __shfl_xor_sync(FM, snd, OFF);               \
        M[r] = addf2(bit ? hi : lo, rcv); } }
#pragma unroll
    for (int qi = 0; qi < 2; qi++) {
        unsigned long long* M = qi ? m1 : m0;
        RSU(M, 16, 8) RSU(M, 8, 4) RSU(M, 4, 2) RSU(M, 2, 1)
        float2 f2 = u2f2(M[0]);
        float snd = (lane & 1) ? f2.x : f2.y;
        float rcv = __shfl_xor_sync(FM, snd, 1);
        float val = ((lane & 1) ? f2.y : f2.x) + rcv;
        g_msg2[((size_t)(b * 1024 + l0 + qi) * 8 + head) * 32 + lane] = val;
    }
#undef RSU
}

// ---- fine level 1: cooperative K gather (fp32 smem), V reuses K buffer ---
__global__ void __launch_bounds__(128) fine1_kernel(const float* __restrict__ wt) {
    __shared__ __align__(16) float kvs[4][64][36];  // K fp32, later V fp16 overlay
    __shared__ __align__(16) float aw[4][64][4];
    __shared__ __align__(16) float qw[4][4][32];
    const int tid = threadIdx.x, w = tid >> 5, lane = tid & 31;
    const int g = blockIdx.x*4 + w;
    const int b = g >> 13, r = g & 8191, h = r >> 10, l2 = r & 1023;
    const int r2 = l2 >> 5, c2 = l2 & 31;

    float w0 = wt[0], w1 = wt[1], w2 = wt[2];
    float wmx = fmaxf(w0, fmaxf(w1, w2));
    float e0 = __expf(w0-wmx), e1 = __expf(w1-wmx), e2 = __expf(w2-wmx);
    float ws0 = e0/(e0+e1+e2), ws1 = e1/(e0+e1+e2);

    int pid = g_idx2[((size_t)(b*8+h)*1024 + l2)*16 + (lane & 15)];
    int p0 = __shfl_sync(FM, pid, lane >> 2);
    int p1 = __shfl_sync(FM, pid, 8 + (lane >> 2));
    int cx = (lane >> 1) & 1, cy = lane & 1;
    int gid0 = (2*(p0>>5)+cx)*64 + 2*(p0&31)+cy;
    int gid1 = (2*(p1>>5)+cx)*64 + 2*(p1&31)+cy;

    const float*  kb  = g_k1t + (size_t)b*4096*256 + h*32;
    const __half* vbh = g_v1h + (size_t)b*4096*256 + h*32;

    // cooperative K gather: 8 lanes per key, 16B chunks
    {
        int sub = lane >> 3, c = lane & 7;
#pragma unroll
        for (int i = 0; i < 16; i++) {
            int K = 4*i + sub;
            int gk = (i < 8) ? __shfl_sync(FM, gid0, K & 31)
                             : __shfl_sync(FM, gid1, K & 31);
            cp16(&kvs[w][K][c*4], kb + (size_t)gk*256 + c*4);
        }
        CP_COMMIT();
    }
    { int t = lane >> 3, f = (lane & 7)*4;
      int qpos = (2*r2 + (t>>1))*64 + 2*c2 + (t&1);
      *(float4*)&qw[w][t][f] = *(const float4*)(g_q1t + ((size_t)(b*4096+qpos))*256 + h*32 + f); }
    CP_WAIT0();
    __syncwarp();

    float4 k0[8], k1[8];
    {
        const float4* kp0 = (const float4*)&kvs[w][lane][0];
        const float4* kp1 = (const float4*)&kvs[w][lane+32][0];
#pragma unroll
        for (int f = 0; f < 8; f++) { k0[f] = kp0[f]; k1[f] = kp1[f]; }
    }
    __syncwarp();  // K register-resident; safe to overwrite buffer with V

    __half* vh = (__half*)&kvs[w][0][0];  // overlay: [64][40] halves
    {
        int sub = lane >> 2, c = lane & 3;
#pragma unroll
        for (int i = 0; i < 8; i++) {
            int K = 8*i + sub;
            int gk = (i < 4) ? __shfl_sync(FM, gid0, K & 31)
                             : __shfl_sync(FM, gid1, K & 31);
            cp16(vh + K*40 + c*8, vbh + (size_t)gk*256 + c*8);
        }
        CP_COMMIT();
    }

    float lg[2][4];
#pragma unroll
    for (int t = 0; t < 4; t++) {
        float a0 = 0.f, a1 = 0.f;
#pragma unroll
        for (int f = 0; f < 8; f++) {
            float4 qf = *(float4*)&qw[w][t][f*4];
            a0 += qf.x*k0[f].x + qf.y*k0[f].y + qf.z*k0[f].z + qf.w*k0[f].w;
            a1 += qf.x*k1[f].x + qf.y*k1[f].y + qf.z*k1[f].z + qf.w*k1[f].w;
        }
        lg[0][t] = a0*SCALE_D; lg[1][t] = a1*SCALE_D;
    }
    float av0[4], av1[4];
#pragma unroll
    for (int t = 0; t < 4; t++) {
        float m = fmaxf(lg[0][t], lg[1][t]);
#pragma unroll
        for (int o = 16; o; o >>= 1) m = fmaxf(m, __shfl_xor_sync(FM, m, o));
        float x0 = __expf(lg[0][t]-m), x1 = __expf(lg[1][t]-m);
        float s = x0 + x1;
#pragma unroll
        for (int o = 16; o; o >>= 1) s += __shfl_xor_sync(FM, s, o);
        av0[t] = x0/s; av1[t] = x1/s;
    }
    *(float4*)&aw[w][lane][0]    = make_float4(av0[0], av0[1], av0[2], av0[3]);
    *(float4*)&aw[w][lane+32][0] = make_float4(av1[0], av1[1], av1[2], av1[3]);

#pragma unroll
    for (int t = 0; t < 4; t++) {
        unsigned o0 = ford(lg[0][t]), o1 = ford(lg[1][t]);
        int keep = 0;
        for (int rr = 0; rr < 8; rr++) {
            unsigned lmx = max(o0, o1);
            unsigned wm = __reduce_max_sync(FM, lmx);
            unsigned ball = __ballot_sync(FM, lmx == wm);
            int src = __ffs(ball) - 1;
            int mysel = (o1 > o0) ? gid1 : gid0;
            int gsel = __shfl_sync(FM, mysel, src);
            if (lane == rr) keep = gsel;
            if (lane == src) { if (o1 > o0) o1 = 0u; else o0 = 0u; }
        }
        int qpos = (2*r2 + (t>>1))*64 + 2*c2 + (t&1);
        if (lane < 8) g_idx1[((size_t)(b*8+h)*4096 + qpos)*8 + lane] = keep;
    }
    CP_WAIT0();
    __syncwarp();
    float acc[4] = {0.f, 0.f, 0.f, 0.f};
#pragma unroll 8
    for (int k = 0; k < 64; k++) {
        float v = __half2float(vh[k * 40 + lane]);
        float4 a4 = *(float4*)&aw[w][k][0];
        acc[0] += a4.x*v; acc[1] += a4.y*v; acc[2] += a4.z*v; acc[3] += a4.w*v;
    }
    float m2 = g_msg2[((size_t)(b*1024+l2)*8 + h)*32 + lane] * ws0;
#pragma unroll
    for (int t = 0; t < 4; t++) {
        int qpos = (2*r2 + (t>>1))*64 + 2*c2 + (t&1);
        g_fin1[((size_t)(b*4096+qpos)*8 + h)*32 + lane] = m2 + acc[t]*ws1;
    }
}

// ---- fine level 0: cooperative fp16 K+V gather via cp.async --------------
__global__ void __launch_bounds__(256) fine0_kernel(const float* __restrict__ wt,
                                                    float* __restrict__ out) {
    extern __shared__ __align__(16) char f0smem[];
    const int tid = threadIdx.x, w = tid >> 5, lane = tid & 31;
    __half* ksh = (__half*)(f0smem + w * 2560);
    __half* vsh = (__half*)(f0smem + 20480 + w * 2560);
    float (*aw)[4] = (float(*)[4])(f0smem + 40960 + w * 512);
    float (*qw)[32] = (float(*)[32])(f0smem + 45056 + w * 512);
    const int g = blockIdx.x*8 + w;
    const int b = g >> 15, r = g & 32767, h = r >> 12, l1 = r & 4095;
    const int R = l1 >> 6, C = l1 & 63;

    float w0 = wt[0], w1 = wt[1], w2 = wt[2];
    float wmx = fmaxf(w0, fmaxf(w1, w2));
    float e0 = __expf(w0-wmx), e1 = __expf(w1-wmx), e2 = __expf(w2-wmx);
    float ws2 = e2/(e0+e1+e2);

    int p = g_idx1[((size_t)(b*8+h)*4096 + l1)*8 + (lane >> 2)];
    int cx = (lane >> 1) & 1, cy = lane & 1;
    int gid = (2*(p>>6)+cx)*128 + 2*(p&63)+cy;

    const __half* kbh = g_k0h + (size_t)b*16384*256 + h*32;
    const __half* vbh = g_v0h + (size_t)b*16384*256 + h*32;

    // cooperative K+V gather: 4 lanes per key, 16B chunks
    {
        int sub = lane >> 2, c = lane & 3;
#pragma unroll
        for (int i = 0; i < 4; i++) {
            int K = 8*i + sub;
            int gk = __shfl_sync(FM, gid, K);
            cp16(ksh + K*40 + c*8, kbh + (size_t)gk*256 + c*8);
            cp16(vsh + K*40 + c*8, vbh + (size_t)gk*256 + c*8);
        }
        CP_COMMIT();
    }
    { int t = lane >> 3, f = (lane & 7)*4;
      int qpos = (2*R + (t>>1))*128 + 2*C + (t&1);
      *(float4*)&qw[t][f] = *(const float4*)(g_q0t + ((size_t)(b*16384+qpos))*256 + h*32 + f); }
    CP_WAIT0();
    __syncwarp();

    float4 kr[8];
    {
        const uint4* kp = (const uint4*)(ksh + lane*40);
#pragma unroll
        for (int f = 0; f < 4; f++) h8_to_f8(kp[f], &kr[2*f], &kr[2*f+1]);
    }

    float lg[4];
#pragma unroll
    for (int t = 0; t < 4; t++) {
        float a = 0.f;
#pragma unroll
        for (int f = 0; f < 8; f++) {
            float4 qf = *(float4*)&qw[t][f*4];
            a += qf.x*kr[f].x + qf.y*kr[f].y + qf.z*kr[f].z + qf.w*kr[f].w;
        }
        lg[t] = a*SCALE_D;
    }
    float av[4];
#pragma unroll
    for (int t = 0; t < 4; t++) {
        float m = lg[t];
#pragma unroll
        for (int o = 16; o; o >>= 1) m = fmaxf(m, __shfl_xor_sync(FM, m, o));
        float x = __expf(lg[t]-m);
        float s = x;
#pragma unroll
        for (int o = 16; o; o >>= 1) s += __shfl_xor_sync(FM, s, o);
        av[t] = x/s;
    }
    *(float4*)&aw[lane][0] = make_float4(av[0], av[1], av[2], av[3]);
    __syncwarp();
    float acc[4] = {0.f, 0.f, 0.f, 0.f};
#pragma unroll 8
    for (int k = 0; k < 32; k++) {
        float v = __half2float(vsh[k * 40 + lane]);
        float4 a4 = *(float4*)&aw[k][0];
        acc[0] += a4.x*v; acc[1] += a4.y*v; acc[2] += a4.z*v; acc[3] += a4.w*v;
    }
    float base = g_fin1[((size_t)(b*4096+l1)*8 + h)*32 + lane];
#pragma unroll
    for (int t = 0; t < 4; t++) {
        int qpos = (2*R + (t>>1))*128 + 2*C + (t&1);
        out[((size_t)(b*16384+qpos)*8 + h)*32 + lane] = base + acc[t]*ws2;
    }
}

extern "C" void kernel_launch(void* const* d_in, const int* in_sizes, int n_in,
                              void* d_out, int out_size) {
    const float* q0 = (const float*)d_in[0];
    const float* q1 = (const float*)d_in[1];
    const float* q2 = (const float*)d_in[2];
    const float* k0 = (const float*)d_in[3];
    const float* k1 = (const float*)d_in[4];
    const float* k2 = (const float*)d_in[5];
    const float* v0 = (const float*)d_in[6];
    const float* v1 = (const float*)d_in[7];
    const float* v2 = (const float*)d_in[8];
    const float* wt = (const float*)d_in[9];

    static cudaStream_t s2;
    static cudaEvent_t evF, evJ;
    static int init = 0;
    if (!init) {
        cudaFuncSetAttribute(coarse_kernel,
                             cudaFuncAttributeMaxDynamicSharedMemorySize, 102400);
        cudaFuncSetAttribute(fine0_kernel,
                             cudaFuncAttributeMaxDynamicSharedMemorySize, 49152);
        cudaStreamCreateWithFlags(&s2, cudaStreamNonBlocking);
        cudaEventCreateWithFlags(&evF, cudaEventDisableTiming);
        cudaEventCreateWithFlags(&evJ, cudaEventDisableTiming);
        init = 1;
    }

    // fork: L0/L1 transposes on side stream, concurrent with tr_l2 + coarse
    cudaEventRecord(evF, 0);
    cudaStreamWaitEvent(s2, evF, 0);
    tr_fast<<<dim3(128, 8, 12), 256, 0, s2>>>(q0, k0, v0, 16384);
    tr_fast<<<dim3(32, 8, 12), 256, 0, s2>>>(q1, k1, v1, 4096);
    cudaEventRecord(evJ, s2);

    // main stream: tiny L2 transpose feeds coarse immediately
    tr_fast<<<dim3(8, 8, 12), 256>>>(q2, k2, v2, 1024);
    coarse_kernel<<<dim3(64, 8, 4), 256, 102400>>>();

    // join: fine levels need both branches
    cudaStreamWaitEvent(0, evJ, 0);
    fine1_kernel<<<8192, 128>>>(wt);
    fine0_kernel<<<16384, 256, 49152>>>(wt, (float*)d_out);
}

// round 16
// speedup vs baseline: 2.1247x; 1.0059x over previous
#include <cuda_runtime.h>
#include <cuda_fp16.h>

#define FM 0xffffffffu
#define SCALE_D 0.17677669529663688f  // 1/sqrt(32)

// ---- scratch (device globals; allocation is forbidden) ----
__device__ float  g_q0t[4*16384*256];
__device__ __half g_k0h[4*16384*256];
__device__ __half g_v0h[4*16384*256];
__device__ float  g_q1t[4*4096*256];
__device__ float  g_k1t[4*4096*256];
__device__ __half g_v1h[4*4096*256];
__device__ float  g_q2t[4*1024*256];
__device__ float  g_k2t[4*1024*256];
__device__ float  g_v2t[4*1024*256];
__device__ float  g_msg2[4*1024*8*32];
__device__ float  g_fin1[4*4096*8*32];
__device__ int    g_idx2[4*8*1024*16];
__device__ int    g_idx1[4*8*4096*8];

__device__ __forceinline__ unsigned ford(float f) {
    unsigned u = __float_as_uint(f);
    return (u & 0x80000000u) ? ~u : (u | 0x80000000u);
}
__device__ __forceinline__ unsigned long long ffma2(unsigned long long a,
                                                    unsigned long long b,
                                                    unsigned long long c) {
    unsigned long long d;
    asm("fma.rn.f32x2 %0, %1, %2, %3;" : "=l"(d) : "l"(a), "l"(b), "l"(c));
    return d;
}
__device__ __forceinline__ unsigned long long addf2(unsigned long long a,
                                                    unsigned long long b) {
    unsigned long long d;
    asm("add.rn.f32x2 %0, %1, %2;" : "=l"(d) : "l"(a), "l"(b));
    return d;
}
__device__ __forceinline__ float2 u2f2(unsigned long long a) {
    float2 r;
    asm("mov.b64 {%0, %1}, %2;" : "=f"(r.x), "=f"(r.y) : "l"(a));
    return r;
}
__device__ __forceinline__ unsigned long long f2u2(float x, float y) {
    unsigned long long r;
    asm("mov.b64 %0, {%1, %2};" : "=l"(r) : "f"(x), "f"(y));
    return r;
}
__device__ __forceinline__ void h8_to_f8(uint4 r, float4* lo, float4* hi) {
    __half2 h0 = *(__half2*)&r.x, h1 = *(__half2*)&r.y;
    __half2 h2 = *(__half2*)&r.z, h3 = *(__half2*)&r.w;
    float2 f0 = __half22float2(h0), f1 = __half22float2(h1);
    float2 f2 = __half22float2(h2), f3 = __half22float2(h3);
    *lo = make_float4(f0.x, f0.y, f1.x, f1.y);
    *hi = make_float4(f2.x, f2.y, f3.x, f3.y);
}
__device__ __forceinline__ void cp16(void* smem_dst, const void* gsrc) {
    unsigned sa = (unsigned)__cvta_generic_to_shared(smem_dst);
    asm volatile("cp.async.cg.shared.global [%0], [%1], 16;\n" :: "r"(sa), "l"(gsrc));
}
#define CP_COMMIT() asm volatile("cp.async.commit_group;\n")
#define CP_WAIT0()  asm volatile("cp.async.wait_group 0;\n")

// ---- float4 transpose (b,256,S) -> (b,S,256); fp16 out for k0,v0,v1 ------
__global__ void __launch_bounds__(256) tr_fast(const float* __restrict__ q,
                                               const float* __restrict__ k,
                                               const float* __restrict__ v, int S) {
    __shared__ float sm[32][132];
    const int which = blockIdx.z >> 2, b = blockIdx.z & 3;
    const float* in = which == 0 ? q : which == 1 ? k : v;
    float* outf = 0; __half* outh = 0;
    if (S == 16384) {
        if (which == 0) outf = g_q0t;
        else if (which == 1) outh = g_k0h;
        else outh = g_v0h;
    } else if (S == 4096) {
        if (which == 0) outf = g_q1t;
        else if (which == 1) outf = g_k1t;
        else outh = g_v1h;
    } else {
        outf = which == 0 ? g_q2t : which == 1 ? g_k2t : g_v2t;
    }
    const int s0 = blockIdx.x * 128, c0 = blockIdx.y * 32;
    const int tid = threadIdx.x, tx = tid & 31, ty = tid >> 5;
    const float* ib = in + (size_t)b * 256 * S;
#pragma unroll
    for (int kk = 0; kk < 4; kk++) {
        int c = ty + 8 * kk;
        *(float4*)&sm[c][4 * tx] = *(const float4*)(ib + (size_t)(c0 + c) * S + s0 + 4 * tx);
    }
    __syncthreads();
    if (outh) {
        __half* ob = outh + (size_t)b * 256 * S;
#pragma unroll
        for (int m = 0; m < 4; m++) {
            int j = tid + 256 * m, sl = j >> 3, cf = j & 7;
            __half2 h0 = __floats2half2_rn(sm[4 * cf][sl], sm[4 * cf + 1][sl]);
            __half2 h1 = __floats2half2_rn(sm[4 * cf + 2][sl], sm[4 * cf + 3][sl]);
            uint2 st;
            st.x = *(unsigned*)&h0; st.y = *(unsigned*)&h1;
            *(uint2*)(ob + (size_t)(s0 + sl) * 256 + c0 + 4 * cf) = st;
        }
    } else {
        float* ob = outf + (size_t)b * 256 * S;
#pragma unroll
        for (int m = 0; m < 4; m++) {
            int j = tid + 256 * m, sl = j >> 3, cf = j & 7;
            float4 o = make_float4(sm[4 * cf][sl], sm[4 * cf + 1][sl],
                                   sm[4 * cf + 2][sl], sm[4 * cf + 3][sl]);
            *(float4*)(ob + (size_t)(s0 + sl) * 256 + c0 + 4 * cf) = o;
        }
    }
}

// ---- coarse: 2 q/warp, f32x2, 128-key tiles, 1 barrier/tile, 4 ILP chains
#define CP_STAGE(GBASE, SMEMT, TID)                                            \
    {                                                                          \
        _Pragma("unroll") for (int it_ = 0; it_ < 4; it_++) {                  \
            int i_ = (TID) + it_ * 256, key_ = i_ >> 3, f_ = i_ & 7;           \
            cp16((SMEMT) + (key_ * 36 + f_ * 4) * 4,                           \
                 (GBASE) + (size_t)key_ * 256 + f_ * 4);                       \
        }                                                                      \
        CP_COMMIT();                                                           \
    }

__global__ void __launch_bounds__(256) coarse_kernel() {
    extern __shared__ __align__(16) char smem_raw[];
    float* As = (float*)smem_raw;  // [16][1024], lane-private access pattern
    const int head = blockIdx.y, b = blockIdx.z;
    const int tid = threadIdx.x, w = tid >> 5, lane = tid & 31;
    const int l0 = blockIdx.x * 16 + 2 * w;
    float* As0 = As + (2 * w) * 1024;
    float* As1 = As0 + 1024;
    char* tileA = smem_raw + 65536;
    char* tileB = tileA + 18432;

    const float* ktb = g_k2t + (size_t)b * 1024 * 256 + head * 32;
    const float* vtb = g_v2t + (size_t)b * 1024 * 256 + head * 32;

    // ---- pass 1: logits into As -----------------------------------------
    {
        unsigned long long q0[16], q1[16];
        const float* qp = g_q2t + ((size_t)(b * 1024 + l0)) * 256 + head * 32;
#pragma unroll
        for (int r = 0; r < 16; r++) {
            q0[r] = *(const unsigned long long*)(qp + 2 * r);
            q1[r] = *(const unsigned long long*)(qp + 256 + 2 * r);
        }
        CP_STAGE(ktb, tileA, tid);
#pragma unroll
        for (int t = 0; t < 8; t++) {
            char* cur = (t & 1) ? tileB : tileA;
            char* nxt = (t & 1) ? tileA : tileB;
            CP_WAIT0();           // tile t landed (this thread's copies)
            __syncthreads();      // publish tile t; retire tile t-1 readers
            if (t < 7) CP_STAGE(ktb + (size_t)(t + 1) * 128 * 256, nxt, tid);
            const float (*ks)[36] = (const float(*)[36])cur;
#pragma unroll
            for (int j = 0; j < 4; j++) {
                int key = j * 32 + lane;
                const ulonglong2* kr = (const ulonglong2*)&ks[key][0];
                unsigned long long a0e = 0ull, a0o = 0ull, a1e = 0ull, a1o = 0ull;
#pragma unroll
                for (int r = 0; r < 8; r++) {
                    ulonglong2 kk = kr[r];
                    a0e = ffma2(q0[2 * r], kk.x, a0e);
                    a0o = ffma2(q0[2 * r + 1], kk.y, a0o);
                    a1e = ffma2(q1[2 * r], kk.x, a1e);
                    a1o = ffma2(q1[2 * r + 1], kk.y, a1o);
                }
                float2 f0 = u2f2(addf2(a0e, a0o)), f1 = u2f2(addf2(a1e, a1o));
                As0[t * 128 + key] = f0.x + f0.y;
                As1[t * 128 + key] = f1.x + f1.y;
            }
        }
    }

    // prefetch first V tile behind the topk/softmax phase.
    // tileA's last readers were tile t=6, retired at t=7's barrier -> safe.
    CP_STAGE(vtb, tileA, tid);

    // ---- top-16 (raw logits; only the SET matters) + softmax -------------
    for (int qi = 0; qi < 2; qi++) {
        float* Aq = qi ? As1 : As0;
        float sc[32];
#pragma unroll
        for (int i = 0; i < 32; i++) sc[i] = Aq[i * 32 + lane];
        unsigned c1 = 0u, c2 = 0u; int i1 = 0, i2 = 0;
#pragma unroll
        for (int i = 0; i < 32; i++) {
            unsigned v = ford(sc[i]);
            if (v > c1) { c2 = c1; i2 = i1; c1 = v; i1 = i; }
            else if (v > c2) { c2 = v; i2 = i; }
        }
        int myidx = 0;
        for (int r = 0; r < 16; r++) {
            unsigned wm = __reduce_max_sync(FM, c1);
            unsigned ball = __ballot_sync(FM, c1 == wm);
            int src = __ffs(ball) - 1;
            int sli = __shfl_sync(FM, i1, src);
            if (lane == r) myidx = sli * 32 + src;
            if (lane == src) {
                if (c2 == 0u) {
                    unsigned a = 0u, bq = 0u; int ai = 0, bi = 0;
#pragma unroll
                    for (int i = 0; i < 32; i++) {
                        unsigned v = ford(sc[i]);
                        if (v < wm) {
                            if (v > a) { bq = a; bi = ai; a = v; ai = i; }
                            else if (v > bq) { bq = v; bi = i; }
                        }
                    }
                    c1 = a; i1 = ai; c2 = bq; i2 = bi;
                } else {
                    c1 = c2; i1 = i2; c2 = 0u;
                }
            }
        }
        if (lane < 16)
            g_idx2[((size_t)(b * 8 + head) * 1024 + l0 + qi) * 16 + lane] = myidx;
        float m = sc[0];
#pragma unroll
        for (int i = 1; i < 32; i++) m = fmaxf(m, sc[i]);
#pragma unroll
        for (int o = 16; o; o >>= 1) m = fmaxf(m, __shfl_xor_sync(FM, m, o));
        float sum = 0.f;
#pragma unroll
        for (int i = 0; i < 32; i++) { sc[i] = __expf((sc[i] - m) * SCALE_D); sum += sc[i]; }
#pragma unroll
        for (int o = 16; o; o >>= 1) sum += __shfl_xor_sync(FM, sum, o);
        float inv = 1.f / sum;
#pragma unroll
        for (int i = 0; i < 32; i++) Aq[i * 32 + lane] = sc[i] * inv;
    }

    // ---- pass 2: A @ V (packed, double buffered, 1 barrier/tile) ---------
    unsigned long long m0[16], m1[16];
#pragma unroll
    for (int r = 0; r < 16; r++) { m0[r] = 0ull; m1[r] = 0ull; }
#pragma unroll
    for (int t = 0; t < 8; t++) {
        char* cur = (t & 1) ? tileB : tileA;
        char* nxt = (t & 1) ? tileA : tileB;
        CP_WAIT0();
        __syncthreads();
        if (t < 7) CP_STAGE(vtb + (size_t)(t + 1) * 128 * 256, nxt, tid);
        const float (*ks)[36] = (const float(*)[36])cur;
#pragma unroll
        for (int j = 0; j < 4; j++) {
            int key = j * 32 + lane, gk = t * 128 + key;
            float a0s = As0[gk], a1s = As1[gk];
            unsigned long long a0 = f2u2(a0s, a0s), a1 = f2u2(a1s, a1s);
            const ulonglong2* vr = (const ulonglong2*)&ks[key][0];
#pragma unroll
            for (int r = 0; r < 8; r++) {
                ulonglong2 vv = vr[r];
                m0[2 * r]     = ffma2(a0, vv.x, m0[2 * r]);
                m0[2 * r + 1] = ffma2(a0, vv.y, m0[2 * r + 1]);
                m1[2 * r]     = ffma2(a1, vv.x, m1[2 * r]);
                m1[2 * r + 1] = ffma2(a1, vv.y, m1[2 * r + 1]);
            }
        }
    }
#define RSU(M, OFF, HALF) { int bit = (lane & OFF) ? 1 : 0;                   \
    _Pragma("unroll") for (int r = 0; r < HALF; r++) {                        \
        unsigned long long lo = M[r], hi = M[HALF + r];                       \
        unsigned long long snd = bit ? lo : hi;                               \
        unsigned long long rcv = __shfl_xor_sync(FM, snd, OFF);               \
        M[r] = addf2(bit ? hi : lo, rcv); } }
#pragma unroll
    for (int qi = 0; qi < 2; qi++) {
        unsigned long long* M = qi ? m1 : m0;
        RSU(M, 16, 8) RSU(M, 8, 4) RSU(M, 4, 2) RSU(M, 2, 1)
        float2 f2 = u2f2(M[0]);
        float snd = (lane & 1) ? f2.x : f2.y;
        float rcv = __shfl_xor_sync(FM, snd, 1);
        float val = ((lane & 1) ? f2.y : f2.x) + rcv;
        g_msg2[((size_t)(b * 1024 + l0 + qi) * 8 + head) * 32 + lane] = val;
    }
#undef RSU
}

// ---- fine level 1: cooperative K gather (fp32 smem), V reuses K buffer ---
__global__ void __launch_bounds__(128) fine1_kernel(const float* __restrict__ wt) {
    __shared__ __align__(16) float kvs[4][64][36];  // K fp32, later V fp16 overlay
    __shared__ __align__(16) float aw[4][64][4];
    __shared__ __align__(16) float qw[4][4][32];
    const int tid = threadIdx.x, w = tid >> 5, lane = tid & 31;
    const int g = blockIdx.x*4 + w;
    const int b = g >> 13, r = g & 8191, h = r >> 10, l2 = r & 1023;
    const int r2 = l2 >> 5, c2 = l2 & 31;

    float w0 = wt[0], w1 = wt[1], w2 = wt[2];
    float wmx = fmaxf(w0, fmaxf(w1, w2));
    float e0 = __expf(w0-wmx), e1 = __expf(w1-wmx), e2 = __expf(w2-wmx);
    float ws0 = e0/(e0+e1+e2), ws1 = e1/(e0+e1+e2);

    int pid = g_idx2[((size_t)(b*8+h)*1024 + l2)*16 + (lane & 15)];
    int p0 = __shfl_sync(FM, pid, lane >> 2);
    int p1 = __shfl_sync(FM, pid, 8 + (lane >> 2));
    int cx = (lane >> 1) & 1, cy = lane & 1;
    int gid0 = (2*(p0>>5)+cx)*64 + 2*(p0&31)+cy;
    int gid1 = (2*(p1>>5)+cx)*64 + 2*(p1&31)+cy;

    const float*  kb  = g_k1t + (size_t)b*4096*256 + h*32;
    const __half* vbh = g_v1h + (size_t)b*4096*256 + h*32;

    // cooperative K gather: 8 lanes per key, 16B chunks
    {
        int sub = lane >> 3, c = lane & 7;
#pragma unroll
        for (int i = 0; i < 16; i++) {
            int K = 4*i + sub;
            int gk = (i < 8) ? __shfl_sync(FM, gid0, K & 31)
                             : __shfl_sync(FM, gid1, K & 31);
            cp16(&kvs[w][K][c*4], kb + (size_t)gk*256 + c*4);
        }
        CP_COMMIT();
    }
    { int t = lane >> 3, f = (lane & 7)*4;
      int qpos = (2*r2 + (t>>1))*64 + 2*c2 + (t&1);
      *(float4*)&qw[w][t][f] = *(const float4*)(g_q1t + ((size_t)(b*4096+qpos))*256 + h*32 + f); }
    CP_WAIT0();
    __syncwarp();

    float4 k0[8], k1[8];
    {
        const float4* kp0 = (const float4*)&kvs[w][lane][0];
        const float4* kp1 = (const float4*)&kvs[w][lane+32][0];
#pragma unroll
        for (int f = 0; f < 8; f++) { k0[f] = kp0[f]; k1[f] = kp1[f]; }
    }
    __syncwarp();  // K register-resident; safe to overwrite buffer with V

    __half* vh = (__half*)&kvs[w][0][0];  // overlay: [64][40] halves
    {
        int sub = lane >> 2, c = lane & 3;
#pragma unroll
        for (int i = 0; i < 8; i++) {
            int K = 8*i + sub;
            int gk = (i < 4) ? __shfl_sync(FM, gid0, K & 31)
                             : __shfl_sync(FM, gid1, K & 31);
            cp16(vh + K*40 + c*8, vbh + (size_t)gk*256 + c*8);
        }
        CP_COMMIT();
    }

    float lg[2][4];
#pragma unroll
    for (int t = 0; t < 4; t++) {
        float a0 = 0.f, a1 = 0.f;
#pragma unroll
        for (int f = 0; f < 8; f++) {
            float4 qf = *(float4*)&qw[w][t][f*4];
            a0 += qf.x*k0[f].x + qf.y*k0[f].y + qf.z*k0[f].z + qf.w*k0[f].w;
            a1 += qf.x*k1[f].x + qf.y*k1[f].y + qf.z*k1[f].z + qf.w*k1[f].w;
        }
        lg[0][t] = a0*SCALE_D; lg[1][t] = a1*SCALE_D;
    }
    float av0[4], av1[4];
#pragma unroll
    for (int t = 0; t < 4; t++) {
        float m = fmaxf(lg[0][t], lg[1][t]);
#pragma unroll
        for (int o = 16; o; o >>= 1) m = fmaxf(m, __shfl_xor_sync(FM, m, o));
        float x0 = __expf(lg[0][t]-m), x1 = __expf(lg[1][t]-m);
        float s = x0 + x1;
#pragma unroll
        for (int o = 16; o; o >>= 1) s += __shfl_xor_sync(FM, s, o);
        av0[t] = x0/s; av1[t] = x1/s;
    }
    *(float4*)&aw[w][lane][0]    = make_float4(av0[0], av0[1], av0[2], av0[3]);
    *(float4*)&aw[w][lane+32][0] = make_float4(av1[0], av1[1], av1[2], av1[3]);

#pragma unroll
    for (int t = 0; t < 4; t++) {
        unsigned o0 = ford(lg[0][t]), o1 = ford(lg[1][t]);
        int keep = 0;
        for (int rr = 0; rr < 8; rr++) {
            unsigned lmx = max(o0, o1);
            unsigned wm = __reduce_max_sync(FM, lmx);
            unsigned ball = __ballot_sync(FM, lmx == wm);
            int src = __ffs(ball) - 1;
            int mysel = (o1 > o0) ? gid1 : gid0;
            int gsel = __shfl_sync(FM, mysel, src);
            if (lane == rr) keep = gsel;
            if (lane == src) { if (o1 > o0) o1 = 0u; else o0 = 0u; }
        }
        int qpos = (2*r2 + (t>>1))*64 + 2*c2 + (t&1);
        if (lane < 8) g_idx1[((size_t)(b*8+h)*4096 + qpos)*8 + lane] = keep;
    }
    CP_WAIT0();
    __syncwarp();
    float acc[4] = {0.f, 0.f, 0.f, 0.f};
#pragma unroll 8
    for (int k = 0; k < 64; k++) {
        float v = __half2float(vh[k * 40 + lane]);
        float4 a4 = *(float4*)&aw[w][k][0];
        acc[0] += a4.x*v; acc[1] += a4.y*v; acc[2] += a4.z*v; acc[3] += a4.w*v;
    }
    float m2 = g_msg2[((size_t)(b*1024+l2)*8 + h)*32 + lane] * ws0;
#pragma unroll
    for (int t = 0; t < 4; t++) {
        int qpos = (2*r2 + (t>>1))*64 + 2*c2 + (t&1);
        g_fin1[((size_t)(b*4096+qpos)*8 + h)*32 + lane] = m2 + acc[t]*ws1;
    }
}

// ---- fine level 0: cooperative fp16 K+V gather via cp.async --------------
__global__ void __launch_bounds__(256) fine0_kernel(const float* __restrict__ wt,
                                                    float* __restrict__ out) {
    extern __shared__ __align__(16) char f0smem[];
    const int tid = threadIdx.x, w = tid >> 5, lane = tid & 31;
    __half* ksh = (__half*)(f0smem + w * 2560);
    __half* vsh = (__half*)(f0smem + 20480 + w * 2560);
    float (*aw)[4] = (float(*)[4])(f0smem + 40960 + w * 512);
    float (*qw)[32] = (float(*)[32])(f0smem + 45056 + w * 512);
    const int g = blockIdx.x*8 + w;
    const int b = g >> 15, r = g & 32767, h = r >> 12, l1 = r & 4095;
    const int R = l1 >> 6, C = l1 & 63;

    float w0 = wt[0], w1 = wt[1], w2 = wt[2];
    float wmx = fmaxf(w0, fmaxf(w1, w2));
    float e0 = __expf(w0-wmx), e1 = __expf(w1-wmx), e2 = __expf(w2-wmx);
    float ws2 = e2/(e0+e1+e2);

    int p = g_idx1[((size_t)(b*8+h)*4096 + l1)*8 + (lane >> 2)];
    int cx = (lane >> 1) & 1, cy = lane & 1;
    int gid = (2*(p>>6)+cx)*128 + 2*(p&63)+cy;

    const __half* kbh = g_k0h + (size_t)b*16384*256 + h*32;
    const __half* vbh = g_v0h + (size_t)b*16384*256 + h*32;

    // cooperative K+V gather: 4 lanes per key, 16B chunks
    {
        int sub = lane >> 2, c = lane & 3;
#pragma unroll
        for (int i = 0; i < 4; i++) {
            int K = 8*i + sub;
            int gk = __shfl_sync(FM, gid, K);
            cp16(ksh + K*40 + c*8, kbh + (size_t)gk*256 + c*8);
            cp16(vsh + K*40 + c*8, vbh + (size_t)gk*256 + c*8);
        }
        CP_COMMIT();
    }
    { int t = lane >> 3, f = (lane & 7)*4;
      int qpos = (2*R + (t>>1))*128 + 2*C + (t&1);
      *(float4*)&qw[t][f] = *(const float4*)(g_q0t + ((size_t)(b*16384+qpos))*256 + h*32 + f); }
    CP_WAIT0();
    __syncwarp();

    float4 kr[8];
    {
        const uint4* kp = (const uint4*)(ksh + lane*40);
#pragma unroll
        for (int f = 0; f < 4; f++) h8_to_f8(kp[f], &kr[2*f], &kr[2*f+1]);
    }

    float lg[4];
#pragma unroll
    for (int t = 0; t < 4; t++) {
        float a = 0.f;
#pragma unroll
        for (int f = 0; f < 8; f++) {
            float4 qf = *(float4*)&qw[t][f*4];
            a += qf.x*kr[f].x + qf.y*kr[f].y + qf.z*kr[f].z + qf.w*kr[f].w;
        }
        lg[t] = a*SCALE_D;
    }
    float av[4];
#pragma unroll
    for (int t = 0; t < 4; t++) {
        float m = lg[t];
#pragma unroll
        for (int o = 16; o; o >>= 1) m = fmaxf(m, __shfl_xor_sync(FM, m, o));
        float x = __expf(lg[t]-m);
        float s = x;
#pragma unroll
        for (int o = 16; o; o >>= 1) s += __shfl_xor_sync(FM, s, o);
        av[t] = x/s;
    }
    *(float4*)&aw[lane][0] = make_float4(av[0], av[1], av[2], av[3]);
    __syncwarp();
    float acc[4] = {0.f, 0.f, 0.f, 0.f};
#pragma unroll 8
    for (int k = 0; k < 32; k++) {
        float v = __half2float(vsh[k * 40 + lane]);
        float4 a4 = *(float4*)&aw[k][0];
        acc[0] += a4.x*v; acc[1] += a4.y*v; acc[2] += a4.z*v; acc[3] += a4.w*v;
    }
    float base = g_fin1[((size_t)(b*4096+l1)*8 + h)*32 + lane];
#pragma unroll
    for (int t = 0; t < 4; t++) {
        int qpos = (2*R + (t>>1))*128 + 2*C + (t&1);
        out[((size_t)(b*16384+qpos)*8 + h)*32 + lane] = base + acc[t]*ws2;
    }
}

extern "C" void kernel_launch(void* const* d_in, const int* in_sizes, int n_in,
                              void* d_out, int out_size) {
    const float* q0 = (const float*)d_in[0];
    const float* q1 = (const float*)d_in[1];
    const float* q2 = (const float*)d_in[2];
    const float* k0 = (const float*)d_in[3];
    const float* k1 = (const float*)d_in[4];
    const float* k2 = (const float*)d_in[5];
    const float* v0 = (const float*)d_in[6];
    const float* v1 = (const float*)d_in[7];
    const float* v2 = (const float*)d_in[8];
    const float* wt = (const float*)d_in[9];

    static cudaStream_t s2;
    static cudaEvent_t evF, evJ;
    static int init = 0;
    if (!init) {
        cudaFuncSetAttribute(coarse_kernel,
                             cudaFuncAttributeMaxDynamicSharedMemorySize, 102400);
        cudaFuncSetAttribute(fine0_kernel,
                             cudaFuncAttributeMaxDynamicSharedMemorySize, 49152);
        cudaStreamCreateWithFlags(&s2, cudaStreamNonBlocking);
        cudaEventCreateWithFlags(&evF, cudaEventDisableTiming);
        cudaEventCreateWithFlags(&evJ, cudaEventDisableTiming);
        init = 1;
    }

    // fork: L0/L1 transposes on side stream, concurrent with tr_l2 + coarse
    cudaEventRecord(evF, 0);
    cudaStreamWaitEvent(s2, evF, 0);
    tr_fast<<<dim3(128, 8, 12), 256, 0, s2>>>(q0, k0, v0, 16384);
    tr_fast<<<dim3(32, 8, 12), 256, 0, s2>>>(q1, k1, v1, 4096);
    cudaEventRecord(evJ, s2);

    // main stream: tiny L2 transpose feeds coarse immediately
    tr_fast<<<dim3(8, 8, 12), 256>>>(q2, k2, v2, 1024);
    coarse_kernel<<<dim3(64, 8, 4), 256, 102400>>>();

    // join: fine levels need both branches
    cudaStreamWaitEvent(0, evJ, 0);
    fine1_kernel<<<8192, 128>>>(wt);
    fine0_kernel<<<16384, 256, 49152>>>(wt, (float*)d_out);
}